// round 1
// baseline (speedup 1.0000x reference)
#include <cuda_runtime.h>
#include <math.h>

#define T_TOK 4096
#define D_DIM 1024
#define I_DIM 4096
#define E_NUM 8
#define SLOTS (2 * T_TOK)

// ---------------- scratch (device globals; no runtime allocation) ----------
__device__ float g_mid[(size_t)SLOTS * I_DIM];    // 134 MB: gelu(h@w1+b1) per slot
__device__ float g_eout[(size_t)SLOTS * D_DIM];   // 33 MB : mid@w2+b2 per slot
__device__ int   g_sel[T_TOK * 2];
__device__ float g_wgt[T_TOK * 2];
__device__ int   g_slot[T_TOK * 2];
__device__ int   g_tok_of_slot[SLOTS];
__device__ int   g_counts[E_NUM];
__device__ int   g_cursor[E_NUM];
__device__ int   g_offsets[E_NUM];

// ---------------- helpers ---------------------------------------------------
__device__ __forceinline__ float gelu_exact(float x) {
    return 0.5f * x * (1.0f + erff(x * 0.70710678118654752f));
}

__device__ __forceinline__ float blockReduceSum256(float v) {
    __shared__ float sm[8];
    #pragma unroll
    for (int o = 16; o; o >>= 1) v += __shfl_xor_sync(0xffffffffu, v, o);
    if ((threadIdx.x & 31) == 0) sm[threadIdx.x >> 5] = v;
    __syncthreads();
    float r = sm[threadIdx.x & 7];
    #pragma unroll
    for (int o = 4; o; o >>= 1) r += __shfl_xor_sync(0xffffffffu, r, o);
    __syncthreads();  // safe reuse of sm on next call
    return r;
}

// ---------------- 0: init ---------------------------------------------------
__global__ void init_kernel() {
    int i = threadIdx.x;
    if (i < E_NUM) { g_counts[i] = 0; g_cursor[i] = 0; }
}

// ---------------- 1: gating -------------------------------------------------
// one block per token; warp e computes dot(h[t], gate_w[e]); thread 0 does
// softmax + top2 + renorm (matches jax.lax.top_k tie-break: lowest index wins)
__global__ void gate_kernel(const float* __restrict__ h,
                            const float* __restrict__ gw) {
    const int t = blockIdx.x;
    const int warp = threadIdx.x >> 5, lane = threadIdx.x & 31;
    const float* hr = h + (size_t)t * D_DIM;
    const float* gr = gw + (size_t)warp * D_DIM;
    float s = 0.f;
    for (int j = lane; j < D_DIM; j += 32) s += hr[j] * gr[j];
    #pragma unroll
    for (int o = 16; o; o >>= 1) s += __shfl_xor_sync(0xffffffffu, s, o);
    __shared__ float lg[E_NUM];
    if (lane == 0) lg[warp] = s;
    __syncthreads();
    if (threadIdx.x == 0) {
        float m = lg[0];
        #pragma unroll
        for (int e = 1; e < E_NUM; e++) m = fmaxf(m, lg[e]);
        float p[E_NUM], den = 0.f;
        #pragma unroll
        for (int e = 0; e < E_NUM; e++) { p[e] = expf(lg[e] - m); den += p[e]; }
        float inv_den = 1.0f / den;
        #pragma unroll
        for (int e = 0; e < E_NUM; e++) p[e] *= inv_den;
        int i0 = 0;
        #pragma unroll
        for (int e = 1; e < E_NUM; e++) if (p[e] > p[i0]) i0 = e;
        int i1 = (i0 == 0) ? 1 : 0;
        #pragma unroll
        for (int e = 0; e < E_NUM; e++)
            if (e != i0 && e != i1 && p[e] > p[i1]) i1 = e;
        float w0 = p[i0], w1 = p[i1];
        float inv = 1.0f / (w0 + w1);
        g_sel[2 * t + 0] = i0; g_sel[2 * t + 1] = i1;
        g_wgt[2 * t + 0] = w0 * inv; g_wgt[2 * t + 1] = w1 * inv;
        atomicAdd(&g_counts[i0], 1);
        atomicAdd(&g_counts[i1], 1);
    }
}

// ---------------- 2: prefix sum + aux loss ----------------------------------
__global__ void prefix_kernel(float* aux_out) {
    if (threadIdx.x == 0) {
        int acc = 0; float aux = 0.f;
        #pragma unroll
        for (int e = 0; e < E_NUM; e++) {
            g_offsets[e] = acc; acc += g_counts[e];
            float u = (float)g_counts[e] / (float)T_TOK - 1.0f / (float)E_NUM;
            aux += u * u;
        }
        if (aux_out) *aux_out = aux / (float)E_NUM;
    }
}

// ---------------- 3: scatter tokens into expert buckets ---------------------
__global__ void scatter_kernel() {
    int t = blockIdx.x * blockDim.x + threadIdx.x;
    if (t >= T_TOK) return;
    #pragma unroll
    for (int k = 0; k < 2; k++) {
        int e = g_sel[2 * t + k];
        int pos = atomicAdd(&g_cursor[e], 1);
        int s = g_offsets[e] + pos;
        g_tok_of_slot[s] = t;
        g_slot[2 * t + k] = s;
    }
}

// ---------------- 4/5: expert GEMMs -----------------------------------------
// C[m][n] = A[m][:] @ B[:][n] (+bias, optional gelu), tiled 64x64x16,
// 256 threads, 4x4 microtile per thread. Rows are slot-indexed per expert;
// grid over-provisioned per expert with early exit.
template <int KD, int ND, bool FIRST>
__global__ void expert_gemm_kernel(const float* __restrict__ h,
                                   const float* __restrict__ W,
                                   const float* __restrict__ bias) {
    const int e = blockIdx.z;
    const int cnt = g_counts[e];
    const int m0 = blockIdx.y * 64;
    if (m0 >= cnt) return;
    const int base = g_offsets[e];
    const int n0 = blockIdx.x * 64;
    const float* __restrict__ B = W + (size_t)e * KD * ND;

    __shared__ float As[16][64];
    __shared__ float Bs[16][64];

    const int tid = threadIdx.x;
    const int tx = tid & 15;
    const int ty = tid >> 4;

    // A-tile loader mapping: each thread loads a float4 along K for one row
    const int arow = tid >> 2;        // 0..63
    const int ak4  = (tid & 3) * 4;   // 0,4,8,12
    int am = m0 + arow;
    int am_c = (am < cnt) ? am : (cnt - 1);
    const float* Arow;
    if (FIRST) {
        int tok = g_tok_of_slot[base + am_c];
        Arow = h + (size_t)tok * KD;
    } else {
        Arow = g_mid + (size_t)(base + am_c) * KD;
    }

    // B-tile loader mapping: float4 along N
    const int brow = tid >> 4;        // 0..15
    const int bn4  = (tid & 15) * 4;  // 0..60
    const float* Bptr = B + (size_t)brow * ND + n0 + bn4;

    float acc[4][4];
    #pragma unroll
    for (int i = 0; i < 4; i++)
        #pragma unroll
        for (int j = 0; j < 4; j++) acc[i][j] = 0.f;

    for (int kt = 0; kt < KD; kt += 16) {
        float4 av = *(const float4*)(Arow + kt + ak4);
        As[ak4 + 0][arow] = av.x;
        As[ak4 + 1][arow] = av.y;
        As[ak4 + 2][arow] = av.z;
        As[ak4 + 3][arow] = av.w;
        float4 bv = *(const float4*)(Bptr + (size_t)kt * ND);
        *(float4*)&Bs[brow][bn4] = bv;
        __syncthreads();
        #pragma unroll
        for (int k = 0; k < 16; k++) {
            float4 a = *(const float4*)&As[k][ty * 4];
            float4 b = *(const float4*)&Bs[k][tx * 4];
            acc[0][0] += a.x * b.x; acc[0][1] += a.x * b.y;
            acc[0][2] += a.x * b.z; acc[0][3] += a.x * b.w;
            acc[1][0] += a.y * b.x; acc[1][1] += a.y * b.y;
            acc[1][2] += a.y * b.z; acc[1][3] += a.y * b.w;
            acc[2][0] += a.z * b.x; acc[2][1] += a.z * b.y;
            acc[2][2] += a.z * b.z; acc[2][3] += a.z * b.w;
            acc[3][0] += a.w * b.x; acc[3][1] += a.w * b.y;
            acc[3][2] += a.w * b.z; acc[3][3] += a.w * b.w;
        }
        __syncthreads();
    }

    const float* be = bias + (size_t)e * ND + n0 + tx * 4;
    float bz[4];
    #pragma unroll
    for (int j = 0; j < 4; j++) bz[j] = be[j];

    #pragma unroll
    for (int i = 0; i < 4; i++) {
        int m = m0 + ty * 4 + i;
        if (m >= cnt) continue;
        float4 o;
        if (FIRST) {
            o.x = gelu_exact(acc[i][0] + bz[0]);
            o.y = gelu_exact(acc[i][1] + bz[1]);
            o.z = gelu_exact(acc[i][2] + bz[2]);
            o.w = gelu_exact(acc[i][3] + bz[3]);
            float* op = g_mid + (size_t)(base + m) * ND + n0 + tx * 4;
            *(float4*)op = o;
        } else {
            o.x = acc[i][0] + bz[0];
            o.y = acc[i][1] + bz[1];
            o.z = acc[i][2] + bz[2];
            o.w = acc[i][3] + bz[3];
            float* op = g_eout + (size_t)(base + m) * ND + n0 + tx * 4;
            *(float4*)op = o;
        }
    }
}

// ---------------- 6: combine + residual + LayerNorm -------------------------
__global__ void combine_ln_kernel(const float* __restrict__ h,
                                  const float* __restrict__ mask,
                                  const float* __restrict__ gamma,
                                  const float* __restrict__ beta,
                                  float* __restrict__ out) {
    const int t = blockIdx.x;
    const float mk = mask[t];
    const int s0 = g_slot[2 * t + 0], s1 = g_slot[2 * t + 1];
    const float w0 = g_wgt[2 * t + 0], w1 = g_wgt[2 * t + 1];
    const float* e0 = g_eout + (size_t)s0 * D_DIM;
    const float* e1 = g_eout + (size_t)s1 * D_DIM;
    const float* hr = h + (size_t)t * D_DIM;

    float y[4];
    float s = 0.f;
    #pragma unroll
    for (int j = 0; j < 4; j++) {
        int d = threadIdx.x + j * 256;
        y[j] = hr[d] + mk * (w0 * e0[d] + w1 * e1[d]);
        s += y[j];
    }
    float mean = blockReduceSum256(s) * (1.0f / D_DIM);
    float vs = 0.f;
    #pragma unroll
    for (int j = 0; j < 4; j++) { float c = y[j] - mean; vs += c * c; }
    float var = blockReduceSum256(vs) * (1.0f / D_DIM);
    float rs = rsqrtf(var + 1e-5f);
    #pragma unroll
    for (int j = 0; j < 4; j++) {
        int d = threadIdx.x + j * 256;
        out[(size_t)t * D_DIM + d] = (y[j] - mean) * rs * gamma[d] + beta[d];
    }
}

// ---------------- launch -----------------------------------------------------
extern "C" void kernel_launch(void* const* d_in, const int* in_sizes, int n_in,
                              void* d_out, int out_size) {
    const float* h     = (const float*)d_in[0];   // (4,1024,1024)
    const float* mask  = (const float*)d_in[1];   // (4,1024)
    const float* gw    = (const float*)d_in[2];   // (8,1024)
    const float* w1    = (const float*)d_in[3];   // (8,1024,4096)
    const float* b1    = (const float*)d_in[4];   // (8,4096)
    const float* w2    = (const float*)d_in[5];   // (8,4096,1024)
    const float* b2    = (const float*)d_in[6];   // (8,1024)
    const float* gamma = (const float*)d_in[7];   // (1024,)
    const float* beta  = (const float*)d_in[8];   // (1024,)
    float* out = (float*)d_out;

    float* aux_ptr = (out_size > T_TOK * D_DIM) ? (out + (size_t)T_TOK * D_DIM)
                                                : nullptr;

    init_kernel<<<1, 32>>>();
    gate_kernel<<<T_TOK, 256>>>(h, gw);
    prefix_kernel<<<1, 1>>>(aux_ptr);
    scatter_kernel<<<(T_TOK + 255) / 256, 256>>>();

    // GEMM1: rows up to 4096 per expert (64 m-tiles), N = I = 4096 (64 n-tiles)
    dim3 g1(I_DIM / 64, 64, E_NUM);
    expert_gemm_kernel<D_DIM, I_DIM, true><<<g1, 256>>>(h, w1, b1);

    // GEMM2: N = D = 1024 (16 n-tiles), K = I = 4096
    dim3 g2(D_DIM / 64, 64, E_NUM);
    expert_gemm_kernel<I_DIM, D_DIM, false><<<g2, 256>>>(h, w2, b2);

    combine_ln_kernel<<<T_TOK, 256>>>(h, mask, gamma, beta, out);
}

// round 2
// speedup vs baseline: 1.4139x; 1.4139x over previous
#include <cuda_runtime.h>
#include <math.h>

#define T_TOK 4096
#define D_DIM 1024
#define I_DIM 4096
#define E_NUM 8
#define SLOTS (2 * T_TOK)

typedef unsigned long long ull;

// ---------------- scratch (device globals; no runtime allocation) ----------
__device__ float g_mid[(size_t)SLOTS * I_DIM];    // 134 MB
__device__ float g_eout[(size_t)SLOTS * D_DIM];   // 33 MB
__device__ int   g_sel[T_TOK * 2];
__device__ float g_wgt[T_TOK * 2];
__device__ int   g_slot[T_TOK * 2];
__device__ int   g_tok_of_slot[SLOTS];
__device__ int   g_counts[E_NUM];
__device__ int   g_cursor[E_NUM];
__device__ int   g_offsets[E_NUM];

// ---------------- packed f32x2 helpers --------------------------------------
__device__ __forceinline__ void fma2(ull& c, ull a, ull b) {
    asm("fma.rn.f32x2 %0, %1, %2, %0;" : "+l"(c) : "l"(a), "l"(b));
}
__device__ __forceinline__ ull dup2(float x) {
    ull r; unsigned xi = __float_as_uint(x);
    asm("mov.b64 %0, {%1, %1};" : "=l"(r) : "r"(xi));
    return r;
}
__device__ __forceinline__ float2 unpk2(ull v) {
    float2 r;
    asm("mov.b64 {%0, %1}, %2;" : "=f"(r.x), "=f"(r.y) : "l"(v));
    return r;
}

__device__ __forceinline__ float gelu_exact(float x) {
    return 0.5f * x * (1.0f + erff(x * 0.70710678118654752f));
}

__device__ __forceinline__ float blockReduceSum256(float v) {
    __shared__ float sm[8];
    #pragma unroll
    for (int o = 16; o; o >>= 1) v += __shfl_xor_sync(0xffffffffu, v, o);
    if ((threadIdx.x & 31) == 0) sm[threadIdx.x >> 5] = v;
    __syncthreads();
    float r = sm[threadIdx.x & 7];
    #pragma unroll
    for (int o = 4; o; o >>= 1) r += __shfl_xor_sync(0xffffffffu, r, o);
    __syncthreads();
    return r;
}

// ---------------- 0: init ---------------------------------------------------
__global__ void init_kernel() {
    int i = threadIdx.x;
    if (i < E_NUM) { g_counts[i] = 0; g_cursor[i] = 0; }
}

// ---------------- 1: gating -------------------------------------------------
__global__ void gate_kernel(const float* __restrict__ h,
                            const float* __restrict__ gw) {
    const int t = blockIdx.x;
    const int warp = threadIdx.x >> 5, lane = threadIdx.x & 31;
    const float* hr = h + (size_t)t * D_DIM;
    const float* gr = gw + (size_t)warp * D_DIM;
    float s = 0.f;
    for (int j = lane; j < D_DIM; j += 32) s += hr[j] * gr[j];
    #pragma unroll
    for (int o = 16; o; o >>= 1) s += __shfl_xor_sync(0xffffffffu, s, o);
    __shared__ float lg[E_NUM];
    if (lane == 0) lg[warp] = s;
    __syncthreads();
    if (threadIdx.x == 0) {
        float m = lg[0];
        #pragma unroll
        for (int e = 1; e < E_NUM; e++) m = fmaxf(m, lg[e]);
        float p[E_NUM], den = 0.f;
        #pragma unroll
        for (int e = 0; e < E_NUM; e++) { p[e] = expf(lg[e] - m); den += p[e]; }
        float inv_den = 1.0f / den;
        #pragma unroll
        for (int e = 0; e < E_NUM; e++) p[e] *= inv_den;
        int i0 = 0;
        #pragma unroll
        for (int e = 1; e < E_NUM; e++) if (p[e] > p[i0]) i0 = e;
        int i1 = (i0 == 0) ? 1 : 0;
        #pragma unroll
        for (int e = 0; e < E_NUM; e++)
            if (e != i0 && e != i1 && p[e] > p[i1]) i1 = e;
        float w0 = p[i0], w1 = p[i1];
        float inv = 1.0f / (w0 + w1);
        g_sel[2 * t + 0] = i0; g_sel[2 * t + 1] = i1;
        g_wgt[2 * t + 0] = w0 * inv; g_wgt[2 * t + 1] = w1 * inv;
        atomicAdd(&g_counts[i0], 1);
        atomicAdd(&g_counts[i1], 1);
    }
}

// ---------------- 2: prefix sum + aux loss ----------------------------------
__global__ void prefix_kernel(float* aux_out) {
    if (threadIdx.x == 0) {
        int acc = 0; float aux = 0.f;
        #pragma unroll
        for (int e = 0; e < E_NUM; e++) {
            g_offsets[e] = acc; acc += g_counts[e];
            float u = (float)g_counts[e] / (float)T_TOK - 1.0f / (float)E_NUM;
            aux += u * u;
        }
        if (aux_out) *aux_out = aux / (float)E_NUM;
    }
}

// ---------------- 3: scatter ------------------------------------------------
__global__ void scatter_kernel() {
    int t = blockIdx.x * blockDim.x + threadIdx.x;
    if (t >= T_TOK) return;
    #pragma unroll
    for (int k = 0; k < 2; k++) {
        int e = g_sel[2 * t + k];
        int pos = atomicAdd(&g_cursor[e], 1);
        int s = g_offsets[e] + pos;
        g_tok_of_slot[s] = t;
        g_slot[2 * t + k] = s;
    }
}

// ---------------- 4/5: expert GEMMs (f32x2 packed, 128x128x16) ---------------
// 256 threads, 8x8 microtile per thread (rows {ty4..+3, 64+ty4..+3},
// cols {tx4..+3, 64+tx4..+3}), m-paired accumulators in fma.rn.f32x2.
template <int KD, int ND, bool FIRST>
__global__ void __launch_bounds__(256, 2)
expert_gemm_kernel(const float* __restrict__ h,
                   const float* __restrict__ W,
                   const float* __restrict__ bias) {
    const int e = blockIdx.z;
    const int cnt = g_counts[e];
    const int m0 = blockIdx.y * 128;
    if (m0 >= cnt) return;
    const int base = g_offsets[e];
    const int n0 = blockIdx.x * 128;
    const float* __restrict__ B = W + (size_t)e * KD * ND;

    __shared__ float As[16][132];   // [k][row], padded
    __shared__ float Bs[16][128];   // [k][col]

    const int tid = threadIdx.x;

    // ---- A loader: one row per thread, two k-quads (akq, akq+8) ----
    const int arow = tid & 127;
    const int akq  = (tid >> 7) * 4;          // 0 or 4
    int am = m0 + arow;
    if (am >= cnt) am = cnt - 1;
    const float* Arow;
    if (FIRST) {
        int tok = g_tok_of_slot[base + am];
        Arow = h + (size_t)tok * KD;
    } else {
        Arow = g_mid + (size_t)(base + am) * KD;
    }

    // ---- B loader: two k rows (bk, bk+8), one float4 along n ----
    const int bk  = tid >> 5;                 // 0..7
    const int bn4 = (tid & 31) * 4;           // 0..124
    const float* Bp = B + (size_t)bk * ND + n0 + bn4;

    const int tx = tid & 15, ty = tid >> 4;
    const int tx4 = tx * 4, ty4 = ty * 4;

    ull acc[4][8];
    #pragma unroll
    for (int p = 0; p < 4; p++)
        #pragma unroll
        for (int c = 0; c < 8; c++) acc[p][c] = 0ULL;

    // prefetch tile 0
    float4 a0 = *(const float4*)(Arow + akq);
    float4 a1 = *(const float4*)(Arow + akq + 8);
    float4 bv0 = *(const float4*)(Bp);
    float4 bv1 = *(const float4*)(Bp + (size_t)8 * ND);

    for (int kt = 0; kt < KD; kt += 16) {
        // commit staged regs to smem
        As[akq + 0][arow] = a0.x; As[akq + 1][arow] = a0.y;
        As[akq + 2][arow] = a0.z; As[akq + 3][arow] = a0.w;
        As[akq + 8][arow] = a1.x; As[akq + 9][arow] = a1.y;
        As[akq +10][arow] = a1.z; As[akq +11][arow] = a1.w;
        *(float4*)&Bs[bk][bn4]     = bv0;
        *(float4*)&Bs[bk + 8][bn4] = bv1;
        __syncthreads();

        // prefetch next tile
        if (kt + 16 < KD) {
            a0  = *(const float4*)(Arow + kt + 16 + akq);
            a1  = *(const float4*)(Arow + kt + 16 + akq + 8);
            bv0 = *(const float4*)(Bp + (size_t)(kt + 16) * ND);
            bv1 = *(const float4*)(Bp + (size_t)(kt + 24) * ND);
        }

        #pragma unroll
        for (int k = 0; k < 16; k++) {
            ull a01 = *(const ull*)&As[k][ty4];
            ull a23 = *(const ull*)&As[k][ty4 + 2];
            ull a45 = *(const ull*)&As[k][64 + ty4];
            ull a67 = *(const ull*)&As[k][64 + ty4 + 2];
            float4 bb0 = *(const float4*)&Bs[k][tx4];
            float4 bb1 = *(const float4*)&Bs[k][64 + tx4];
            ull b[8];
            b[0] = dup2(bb0.x); b[1] = dup2(bb0.y);
            b[2] = dup2(bb0.z); b[3] = dup2(bb0.w);
            b[4] = dup2(bb1.x); b[5] = dup2(bb1.y);
            b[6] = dup2(bb1.z); b[7] = dup2(bb1.w);
            #pragma unroll
            for (int c = 0; c < 8; c++) {
                fma2(acc[0][c], a01, b[c]);
                fma2(acc[1][c], a23, b[c]);
                fma2(acc[2][c], a45, b[c]);
                fma2(acc[3][c], a67, b[c]);
            }
        }
        __syncthreads();
    }

    // ---- epilogue: bias (+gelu for FIRST), guarded vectorized stores ----
    const float* be = bias + (size_t)e * ND + n0;
    float bz[8];
    #pragma unroll
    for (int c = 0; c < 4; c++) { bz[c] = be[tx4 + c]; bz[c + 4] = be[64 + tx4 + c]; }

    float* outbase = FIRST ? (g_mid + (size_t)base * ND)
                           : (g_eout + (size_t)base * ND);

    #pragma unroll
    for (int p = 0; p < 4; p++) {
        int rbase = ty4 + (p >> 1) * 64 + (p & 1) * 2;
        float2 v[8];
        #pragma unroll
        for (int c = 0; c < 8; c++) v[c] = unpk2(acc[p][c]);
        #pragma unroll
        for (int s = 0; s < 2; s++) {
            int m = m0 + rbase + s;
            if (m >= cnt) continue;
            float r[8];
            #pragma unroll
            for (int c = 0; c < 8; c++) {
                float val = (s == 0 ? v[c].x : v[c].y) + bz[c];
                r[c] = FIRST ? gelu_exact(val) : val;
            }
            float* op = outbase + (size_t)m * ND + n0;
            float4 o0 = make_float4(r[0], r[1], r[2], r[3]);
            float4 o1 = make_float4(r[4], r[5], r[6], r[7]);
            *(float4*)(op + tx4)      = o0;
            *(float4*)(op + 64 + tx4) = o1;
        }
    }
}

// ---------------- 6: combine + residual + LayerNorm -------------------------
__global__ void combine_ln_kernel(const float* __restrict__ h,
                                  const float* __restrict__ mask,
                                  const float* __restrict__ gamma,
                                  const float* __restrict__ beta,
                                  float* __restrict__ out) {
    const int t = blockIdx.x;
    const float mk = mask[t];
    const int s0 = g_slot[2 * t + 0], s1 = g_slot[2 * t + 1];
    const float w0 = g_wgt[2 * t + 0], w1 = g_wgt[2 * t + 1];
    const float* e0 = g_eout + (size_t)s0 * D_DIM;
    const float* e1 = g_eout + (size_t)s1 * D_DIM;
    const float* hr = h + (size_t)t * D_DIM;

    float y[4];
    float s = 0.f;
    #pragma unroll
    for (int j = 0; j < 4; j++) {
        int d = threadIdx.x + j * 256;
        y[j] = hr[d] + mk * (w0 * e0[d] + w1 * e1[d]);
        s += y[j];
    }
    float mean = blockReduceSum256(s) * (1.0f / D_DIM);
    float vs = 0.f;
    #pragma unroll
    for (int j = 0; j < 4; j++) { float c = y[j] - mean; vs += c * c; }
    float var = blockReduceSum256(vs) * (1.0f / D_DIM);
    float rs = rsqrtf(var + 1e-5f);
    #pragma unroll
    for (int j = 0; j < 4; j++) {
        int d = threadIdx.x + j * 256;
        out[(size_t)t * D_DIM + d] = (y[j] - mean) * rs * gamma[d] + beta[d];
    }
}

// ---------------- launch -----------------------------------------------------
extern "C" void kernel_launch(void* const* d_in, const int* in_sizes, int n_in,
                              void* d_out, int out_size) {
    const float* h     = (const float*)d_in[0];
    const float* mask  = (const float*)d_in[1];
    const float* gw    = (const float*)d_in[2];
    const float* w1    = (const float*)d_in[3];
    const float* b1    = (const float*)d_in[4];
    const float* w2    = (const float*)d_in[5];
    const float* b2    = (const float*)d_in[6];
    const float* gamma = (const float*)d_in[7];
    const float* beta  = (const float*)d_in[8];
    float* out = (float*)d_out;

    float* aux_ptr = (out_size > T_TOK * D_DIM) ? (out + (size_t)T_TOK * D_DIM)
                                                : nullptr;

    init_kernel<<<1, 32>>>();
    gate_kernel<<<T_TOK, 256>>>(h, gw);
    prefix_kernel<<<1, 1>>>(aux_ptr);
    scatter_kernel<<<(T_TOK + 255) / 256, 256>>>();

    // GEMM1: N = I = 4096 (32 n-tiles), up to 8192 rows (64 m-tiles)
    dim3 g1(I_DIM / 128, 64, E_NUM);
    expert_gemm_kernel<D_DIM, I_DIM, true><<<g1, 256>>>(h, w1, b1);

    // GEMM2: N = D = 1024 (8 n-tiles), K = I = 4096
    dim3 g2(D_DIM / 128, 64, E_NUM);
    expert_gemm_kernel<I_DIM, D_DIM, false><<<g2, 256>>>(h, w2, b2);

    combine_ln_kernel<<<T_TOK, 256>>>(h, mask, gamma, beta, out);
}

// round 4
// speedup vs baseline: 2.1665x; 1.5323x over previous
#include <cuda_runtime.h>
#include <cuda_bf16.h>
#include <math.h>

typedef unsigned int       u32;
typedef unsigned long long u64;

#define T_TOK 4096
#define D_DIM 1024
#define I_DIM 4096
#define E_NUM 8
#define SLOTS (2 * T_TOK)

// ---------------- scratch (device globals; no runtime allocation) ----------
__device__ __nv_bfloat16 g_h_hi[(size_t)T_TOK * D_DIM];
__device__ __nv_bfloat16 g_h_lo[(size_t)T_TOK * D_DIM];
__device__ __nv_bfloat16 g_w1t_hi[(size_t)E_NUM * I_DIM * D_DIM];  // [E][I][D]
__device__ __nv_bfloat16 g_w1t_lo[(size_t)E_NUM * I_DIM * D_DIM];
__device__ __nv_bfloat16 g_w2t_hi[(size_t)E_NUM * D_DIM * I_DIM];  // [E][D][I]
__device__ __nv_bfloat16 g_w2t_lo[(size_t)E_NUM * D_DIM * I_DIM];
__device__ __nv_bfloat16 g_mid_hi[(size_t)SLOTS * I_DIM];
__device__ __nv_bfloat16 g_mid_lo[(size_t)SLOTS * I_DIM];
__device__ float g_eout[(size_t)SLOTS * D_DIM];
__device__ int   g_sel[T_TOK * 2];
__device__ float g_wgt[T_TOK * 2];
__device__ int   g_slot[T_TOK * 2];
__device__ int   g_tok_of_slot[SLOTS];
__device__ int   g_counts[E_NUM];
__device__ int   g_cursor[E_NUM];
__device__ int   g_offsets[E_NUM];

// ---------------- PTX helpers (sm_80-level: cp.async / ldmatrix / mma) ------
__device__ __forceinline__ u32 smem_u32(const void* p) {
    u32 a;
    asm("{ .reg .u64 t; cvta.to.shared.u64 t, %1; cvt.u32.u64 %0, t; }"
        : "=r"(a) : "l"(p));
    return a;
}

#define CPA16(d, s) \
    asm volatile("cp.async.cg.shared.global [%0], [%1], 16;" \
                 :: "r"(d), "l"(s) : "memory")
#define CPA_COMMIT() asm volatile("cp.async.commit_group;" ::: "memory")
#define CPA_WAIT1()  asm volatile("cp.async.wait_group 1;" ::: "memory")
#define CPA_WAIT0()  asm volatile("cp.async.wait_group 0;" ::: "memory")

#define LDSM4(r0, r1, r2, r3, a) \
    asm volatile("ldmatrix.sync.aligned.m8n8.x4.shared.b16 {%0,%1,%2,%3}, [%4];" \
                 : "=r"(r0), "=r"(r1), "=r"(r2), "=r"(r3) : "r"(a))

#define MMA16816(c, a, b0, b1) \
    asm volatile("mma.sync.aligned.m16n8k16.row.col.f32.bf16.bf16.f32 " \
                 "{%0,%1,%2,%3}, {%4,%5,%6,%7}, {%8,%9}, {%0,%1,%2,%3};" \
                 : "+f"((c)[0]), "+f"((c)[1]), "+f"((c)[2]), "+f"((c)[3]) \
                 : "r"((a)[0]), "r"((a)[1]), "r"((a)[2]), "r"((a)[3]), \
                   "r"(b0), "r"(b1))

__device__ __forceinline__ float gelu_exact(float x) {
    return 0.5f * x * (1.0f + erff(x * 0.70710678118654752f));
}

// ---------------- 0: init ---------------------------------------------------
__global__ void init_kernel() {
    int i = threadIdx.x;
    if (i < E_NUM) { g_counts[i] = 0; g_cursor[i] = 0; }
}

// ---------------- 1: gating -------------------------------------------------
__global__ void gate_kernel(const float* __restrict__ h,
                            const float* __restrict__ gw) {
    const int t = blockIdx.x;
    const int warp = threadIdx.x >> 5, lane = threadIdx.x & 31;
    const float* hr = h + (size_t)t * D_DIM;
    const float* gr = gw + (size_t)warp * D_DIM;
    float s = 0.f;
    for (int j = lane; j < D_DIM; j += 32) s += hr[j] * gr[j];
    #pragma unroll
    for (int o = 16; o; o >>= 1) s += __shfl_xor_sync(0xffffffffu, s, o);
    __shared__ float lg[E_NUM];
    if (lane == 0) lg[warp] = s;
    __syncthreads();
    if (threadIdx.x == 0) {
        float m = lg[0];
        #pragma unroll
        for (int e = 1; e < E_NUM; e++) m = fmaxf(m, lg[e]);
        float p[E_NUM], den = 0.f;
        #pragma unroll
        for (int e = 0; e < E_NUM; e++) { p[e] = expf(lg[e] - m); den += p[e]; }
        float inv_den = 1.0f / den;
        #pragma unroll
        for (int e = 0; e < E_NUM; e++) p[e] *= inv_den;
        int i0 = 0;
        #pragma unroll
        for (int e = 1; e < E_NUM; e++) if (p[e] > p[i0]) i0 = e;
        int i1 = (i0 == 0) ? 1 : 0;
        #pragma unroll
        for (int e = 0; e < E_NUM; e++)
            if (e != i0 && e != i1 && p[e] > p[i1]) i1 = e;
        float w0 = p[i0], w1 = p[i1];
        float inv = 1.0f / (w0 + w1);
        g_sel[2 * t + 0] = i0; g_sel[2 * t + 1] = i1;
        g_wgt[2 * t + 0] = w0 * inv; g_wgt[2 * t + 1] = w1 * inv;
        atomicAdd(&g_counts[i0], 1);
        atomicAdd(&g_counts[i1], 1);
    }
}

// ---------------- 2: prefix sum + aux loss ----------------------------------
__global__ void prefix_kernel(float* aux_out) {
    if (threadIdx.x == 0) {
        int acc = 0; float aux = 0.f;
        #pragma unroll
        for (int e = 0; e < E_NUM; e++) {
            g_offsets[e] = acc; acc += g_counts[e];
            float u = (float)g_counts[e] / (float)T_TOK - 1.0f / (float)E_NUM;
            aux += u * u;
        }
        if (aux_out) *aux_out = aux / (float)E_NUM;
    }
}

// ---------------- 3: scatter ------------------------------------------------
__global__ void scatter_kernel() {
    int t = blockIdx.x * blockDim.x + threadIdx.x;
    if (t >= T_TOK) return;
    #pragma unroll
    for (int k = 0; k < 2; k++) {
        int e = g_sel[2 * t + k];
        int pos = atomicAdd(&g_cursor[e], 1);
        int s = g_offsets[e] + pos;
        g_tok_of_slot[s] = t;
        g_slot[2 * t + k] = s;
    }
}

// ---------------- 4: split h into bf16 hi/lo --------------------------------
__global__ void split_h_kernel(const float* __restrict__ h) {
    int i = blockIdx.x * 256 + threadIdx.x;   // float4 index
    float4 v = ((const float4*)h)[i];
    __nv_bfloat16 h0 = __float2bfloat16(v.x), h1 = __float2bfloat16(v.y);
    __nv_bfloat16 h2 = __float2bfloat16(v.z), h3 = __float2bfloat16(v.w);
    __nv_bfloat16 l0 = __float2bfloat16(v.x - __bfloat162float(h0));
    __nv_bfloat16 l1 = __float2bfloat16(v.y - __bfloat162float(h1));
    __nv_bfloat16 l2 = __float2bfloat16(v.z - __bfloat162float(h2));
    __nv_bfloat16 l3 = __float2bfloat16(v.w - __bfloat162float(h3));
    u32 a = (u32)__bfloat16_as_ushort(h0) | ((u32)__bfloat16_as_ushort(h1) << 16);
    u32 b = (u32)__bfloat16_as_ushort(h2) | ((u32)__bfloat16_as_ushort(h3) << 16);
    u32 c = (u32)__bfloat16_as_ushort(l0) | ((u32)__bfloat16_as_ushort(l1) << 16);
    u32 d = (u32)__bfloat16_as_ushort(l2) | ((u32)__bfloat16_as_ushort(l3) << 16);
    ((uint2*)g_h_hi)[i] = make_uint2(a, b);
    ((uint2*)g_h_lo)[i] = make_uint2(c, d);
}

// ---------------- 5: transpose + split weights ------------------------------
// W [E][KDIM][NDIM] fp32 -> [E][NDIM][KDIM] bf16 hi/lo
template <bool W1>
__global__ void tsplit_kernel(const float* __restrict__ W) {
    const int KDIM = W1 ? D_DIM : I_DIM;
    const int NDIM = W1 ? I_DIM : D_DIM;
    __shared__ float t[32][33];
    const int e = blockIdx.z;
    const int n0 = blockIdx.x * 32, k0 = blockIdx.y * 32;
    const int tx = threadIdx.x, ty = threadIdx.y;  // (32, 8)
    const float* Wp = W + (size_t)e * KDIM * NDIM;
    #pragma unroll
    for (int j = 0; j < 4; j++)
        t[ty + 8 * j][tx] = Wp[(size_t)(k0 + ty + 8 * j) * NDIM + n0 + tx];
    __syncthreads();
    __nv_bfloat16* oh = W1 ? g_w1t_hi : g_w2t_hi;
    __nv_bfloat16* ol = W1 ? g_w1t_lo : g_w2t_lo;
    #pragma unroll
    for (int j = 0; j < 4; j++) {
        float x = t[tx][ty + 8 * j];
        int n = n0 + ty + 8 * j, k = k0 + tx;
        __nv_bfloat16 hh = __float2bfloat16(x);
        __nv_bfloat16 ll = __float2bfloat16(x - __bfloat162float(hh));
        size_t o = (size_t)e * NDIM * KDIM + (size_t)n * KDIM + k;
        oh[o] = hh; ol[o] = ll;
    }
}

// ---------------- 6/7: expert GEMMs via mma.sync (HMMA bf16, 3-pass) --------
// Block tile 128x128x32, 256 thr, 8 warps (2m x 4n), warp tile 64x32.
// smem per stage: 4 matrices x 128 rows x 80B = 40960 B, double buffered.
#define ROWB   80
#define MATB   (128 * ROWB)       // 10240
#define STAGEB (4 * MATB)         // 40960
#define GSMEM_BYTES (2 * STAGEB)  // 81920

template <int KD, int ND, bool FIRST>
__global__ void __launch_bounds__(256, 1)
mma_gemm_kernel(const float* __restrict__ bias) {
    const int e = blockIdx.z;
    const int cnt = g_counts[e];
    const int m0 = blockIdx.y * 128;
    if (m0 >= cnt) return;
    const int base = g_offsets[e];
    const int n0 = blockIdx.x * 128;

    extern __shared__ char smem[];
    const u32 sb = smem_u32(smem);

    const int tid  = threadIdx.x;
    const int lane = tid & 31, wid = tid >> 5;

    // ---- loader mapping: thread -> (row 0..127, k-half 0/1) ----
    const int lrow = tid >> 1;
    const int lkh  = (tid & 1) * 16;           // element offset in k-tile
    int am = m0 + lrow; if (am >= cnt) am = cnt - 1;
    const __nv_bfloat16 *pa_hi, *pa_lo;
    if (FIRST) {
        int tok = g_tok_of_slot[base + am];
        pa_hi = g_h_hi + (size_t)tok * KD;
        pa_lo = g_h_lo + (size_t)tok * KD;
    } else {
        pa_hi = g_mid_hi + (size_t)(base + am) * KD;
        pa_lo = g_mid_lo + (size_t)(base + am) * KD;
    }
    const __nv_bfloat16* pb_hi =
        (FIRST ? g_w1t_hi : g_w2t_hi) + ((size_t)e * ND + n0 + lrow) * KD;
    const __nv_bfloat16* pb_lo =
        (FIRST ? g_w1t_lo : g_w2t_lo) + ((size_t)e * ND + n0 + lrow) * KD;
    const u32 doff = (u32)(lrow * ROWB + (tid & 1) * 32);

    float c[4][4][4];
    #pragma unroll
    for (int i = 0; i < 4; i++)
        #pragma unroll
        for (int f = 0; f < 4; f++)
            #pragma unroll
            for (int q = 0; q < 4; q++) c[i][f][q] = 0.f;

    const int wm = (wid & 1) * 64;
    const int wn = (wid >> 1) * 32;
    const int l15 = lane & 15;
    const int lk16 = (lane >> 4) * 16;          // byte offset for k-half

    const int NK = KD / 32;

    // prologue: stage 0
    {
        const __nv_bfloat16* s0 = pa_hi + lkh;
        const __nv_bfloat16* s1 = pa_lo + lkh;
        const __nv_bfloat16* s2 = pb_hi + lkh;
        const __nv_bfloat16* s3 = pb_lo + lkh;
        u32 d = sb + doff;
        CPA16(d + 0 * MATB,      s0); CPA16(d + 0 * MATB + 16, s0 + 8);
        CPA16(d + 1 * MATB,      s1); CPA16(d + 1 * MATB + 16, s1 + 8);
        CPA16(d + 2 * MATB,      s2); CPA16(d + 2 * MATB + 16, s2 + 8);
        CPA16(d + 3 * MATB,      s3); CPA16(d + 3 * MATB + 16, s3 + 8);
    }
    CPA_COMMIT();

    #pragma unroll 1
    for (int kc = 0; kc < NK; kc++) {
        if (kc + 1 < NK) {
            const int kt = (kc + 1) * 32;
            const __nv_bfloat16* s0 = pa_hi + kt + lkh;
            const __nv_bfloat16* s1 = pa_lo + kt + lkh;
            const __nv_bfloat16* s2 = pb_hi + kt + lkh;
            const __nv_bfloat16* s3 = pb_lo + kt + lkh;
            u32 d = sb + ((kc + 1) & 1) * STAGEB + doff;
            CPA16(d + 0 * MATB,      s0); CPA16(d + 0 * MATB + 16, s0 + 8);
            CPA16(d + 1 * MATB,      s1); CPA16(d + 1 * MATB + 16, s1 + 8);
            CPA16(d + 2 * MATB,      s2); CPA16(d + 2 * MATB + 16, s2 + 8);
            CPA16(d + 3 * MATB,      s3); CPA16(d + 3 * MATB + 16, s3 + 8);
            CPA_COMMIT();
            CPA_WAIT1();
        } else {
            CPA_COMMIT();
            CPA_WAIT0();
        }
        __syncthreads();

        const u32 stb = sb + (kc & 1) * STAGEB;
        const u32 Ah = stb, Al = stb + MATB, Bh = stb + 2 * MATB, Bl = stb + 3 * MATB;

        #pragma unroll
        for (int s = 0; s < 2; s++) {
            const u32 koff = (u32)(s * 32 + lk16);
            u32 ah[4][4], al[4][4], bh[8], bl[8];
            #pragma unroll
            for (int i = 0; i < 4; i++) {
                u32 ra = (u32)((wm + i * 16 + l15) * ROWB) + koff;
                LDSM4(ah[i][0], ah[i][1], ah[i][2], ah[i][3], Ah + ra);
                LDSM4(al[i][0], al[i][1], al[i][2], al[i][3], Al + ra);
            }
            #pragma unroll
            for (int j = 0; j < 2; j++) {
                u32 rb = (u32)((wn + j * 16 + l15) * ROWB) + koff;
                LDSM4(bh[j*4+0], bh[j*4+1], bh[j*4+2], bh[j*4+3], Bh + rb);
                LDSM4(bl[j*4+0], bl[j*4+1], bl[j*4+2], bl[j*4+3], Bl + rb);
            }
            // pass 1: a_hi * b_hi
            #pragma unroll
            for (int i = 0; i < 4; i++)
                #pragma unroll
                for (int f = 0; f < 4; f++) {
                    int j = f >> 1, r = f & 1;
                    MMA16816(c[i][f], ah[i], bh[j*4 + r], bh[j*4 + r + 2]);
                }
            // pass 2: a_hi * b_lo
            #pragma unroll
            for (int i = 0; i < 4; i++)
                #pragma unroll
                for (int f = 0; f < 4; f++) {
                    int j = f >> 1, r = f & 1;
                    MMA16816(c[i][f], ah[i], bl[j*4 + r], bl[j*4 + r + 2]);
                }
            // pass 3: a_lo * b_hi
            #pragma unroll
            for (int i = 0; i < 4; i++)
                #pragma unroll
                for (int f = 0; f < 4; f++) {
                    int j = f >> 1, r = f & 1;
                    MMA16816(c[i][f], al[i], bh[j*4 + r], bh[j*4 + r + 2]);
                }
        }
        __syncthreads();
    }

    // ---- epilogue ----
    #pragma unroll
    for (int f = 0; f < 4; f++) {
        const int ncol = n0 + wn + f * 8 + (lane & 3) * 2;
        const float bz0 = bias[(size_t)e * ND + ncol];
        const float bz1 = bias[(size_t)e * ND + ncol + 1];
        #pragma unroll
        for (int i = 0; i < 4; i++) {
            const int mr0 = m0 + wm + i * 16 + (lane >> 2);
            #pragma unroll
            for (int half = 0; half < 2; half++) {
                const int m = mr0 + half * 8;
                if (m >= cnt) continue;
                float v0 = c[i][f][half * 2 + 0] + bz0;
                float v1 = c[i][f][half * 2 + 1] + bz1;
                const size_t off = (size_t)(base + m) * ND + ncol;
                if (FIRST) {
                    float y0 = gelu_exact(v0), y1 = gelu_exact(v1);
                    __nv_bfloat16 h0 = __float2bfloat16(y0);
                    __nv_bfloat16 h1 = __float2bfloat16(y1);
                    __nv_bfloat16 l0 = __float2bfloat16(y0 - __bfloat162float(h0));
                    __nv_bfloat16 l1 = __float2bfloat16(y1 - __bfloat162float(h1));
                    *(u32*)(g_mid_hi + off) =
                        (u32)__bfloat16_as_ushort(h0) | ((u32)__bfloat16_as_ushort(h1) << 16);
                    *(u32*)(g_mid_lo + off) =
                        (u32)__bfloat16_as_ushort(l0) | ((u32)__bfloat16_as_ushort(l1) << 16);
                } else {
                    *(float2*)(g_eout + off) = make_float2(v0, v1);
                }
            }
        }
    }
}

// ---------------- 8: combine + residual + LayerNorm -------------------------
__device__ __forceinline__ float blockReduceSum256(float v) {
    __shared__ float sm[8];
    #pragma unroll
    for (int o = 16; o; o >>= 1) v += __shfl_xor_sync(0xffffffffu, v, o);
    if ((threadIdx.x & 31) == 0) sm[threadIdx.x >> 5] = v;
    __syncthreads();
    float r = sm[threadIdx.x & 7];
    #pragma unroll
    for (int o = 4; o; o >>= 1) r += __shfl_xor_sync(0xffffffffu, r, o);
    __syncthreads();
    return r;
}

__global__ void combine_ln_kernel(const float* __restrict__ h,
                                  const float* __restrict__ mask,
                                  const float* __restrict__ gamma,
                                  const float* __restrict__ beta,
                                  float* __restrict__ out) {
    const int t = blockIdx.x;
    const float mk = mask[t];
    const int s0 = g_slot[2 * t + 0], s1 = g_slot[2 * t + 1];
    const float w0 = g_wgt[2 * t + 0], w1 = g_wgt[2 * t + 1];
    const float* e0 = g_eout + (size_t)s0 * D_DIM;
    const float* e1 = g_eout + (size_t)s1 * D_DIM;
    const float* hr = h + (size_t)t * D_DIM;

    float y[4];
    float s = 0.f;
    #pragma unroll
    for (int j = 0; j < 4; j++) {
        int d = threadIdx.x + j * 256;
        y[j] = hr[d] + mk * (w0 * e0[d] + w1 * e1[d]);
        s += y[j];
    }
    float mean = blockReduceSum256(s) * (1.0f / D_DIM);
    float vs = 0.f;
    #pragma unroll
    for (int j = 0; j < 4; j++) { float c = y[j] - mean; vs += c * c; }
    float var = blockReduceSum256(vs) * (1.0f / D_DIM);
    float rs = rsqrtf(var + 1e-5f);
    #pragma unroll
    for (int j = 0; j < 4; j++) {
        int d = threadIdx.x + j * 256;
        out[(size_t)t * D_DIM + d] = (y[j] - mean) * rs * gamma[d] + beta[d];
    }
}

// ---------------- launch -----------------------------------------------------
extern "C" void kernel_launch(void* const* d_in, const int* in_sizes, int n_in,
                              void* d_out, int out_size) {
    const float* h     = (const float*)d_in[0];
    const float* mask  = (const float*)d_in[1];
    const float* gw    = (const float*)d_in[2];
    const float* w1    = (const float*)d_in[3];
    const float* b1    = (const float*)d_in[4];
    const float* w2    = (const float*)d_in[5];
    const float* b2    = (const float*)d_in[6];
    const float* gamma = (const float*)d_in[7];
    const float* beta  = (const float*)d_in[8];
    float* out = (float*)d_out;

    float* aux_ptr = (out_size > T_TOK * D_DIM) ? (out + (size_t)T_TOK * D_DIM)
                                                : nullptr;

    cudaFuncSetAttribute(mma_gemm_kernel<D_DIM, I_DIM, true>,
                         cudaFuncAttributeMaxDynamicSharedMemorySize, GSMEM_BYTES);
    cudaFuncSetAttribute(mma_gemm_kernel<I_DIM, D_DIM, false>,
                         cudaFuncAttributeMaxDynamicSharedMemorySize, GSMEM_BYTES);

    init_kernel<<<1, 32>>>();
    gate_kernel<<<T_TOK, 256>>>(h, gw);
    prefix_kernel<<<1, 1>>>(aux_ptr);
    scatter_kernel<<<(T_TOK + 255) / 256, 256>>>();

    split_h_kernel<<<(T_TOK * D_DIM / 4) / 256, 256>>>(h);
    { dim3 g(I_DIM / 32, D_DIM / 32, E_NUM); tsplit_kernel<true><<<g, dim3(32, 8)>>>(w1); }
    { dim3 g(D_DIM / 32, I_DIM / 32, E_NUM); tsplit_kernel<false><<<g, dim3(32, 8)>>>(w2); }

    // GEMM1: M = cnt_e (<= 4096), N = I_DIM, K = D_DIM
    { dim3 g(I_DIM / 128, T_TOK / 128, E_NUM);
      mma_gemm_kernel<D_DIM, I_DIM, true><<<g, 256, GSMEM_BYTES>>>(b1); }
    // GEMM2: N = D_DIM, K = I_DIM
    { dim3 g(D_DIM / 128, T_TOK / 128, E_NUM);
      mma_gemm_kernel<I_DIM, D_DIM, false><<<g, 256, GSMEM_BYTES>>>(b2); }

    combine_ln_kernel<<<T_TOK, 256>>>(h, mask, gamma, beta, out);
}

// round 5
// speedup vs baseline: 2.2189x; 1.0242x over previous
#include <cuda_runtime.h>
#include <cuda_bf16.h>
#include <math.h>

typedef unsigned int       u32;
typedef unsigned long long u64;

#define T_TOK 4096
#define D_DIM 1024
#define I_DIM 4096
#define E_NUM 8
#define SLOTS (2 * T_TOK)

// ---------------- scratch (device globals; no runtime allocation) ----------
__device__ __nv_bfloat16 g_h_hi[(size_t)T_TOK * D_DIM];
__device__ __nv_bfloat16 g_h_lo[(size_t)T_TOK * D_DIM];
__device__ __nv_bfloat16 g_w1t_hi[(size_t)E_NUM * I_DIM * D_DIM];  // [E][I][D]
__device__ __nv_bfloat16 g_w1t_lo[(size_t)E_NUM * I_DIM * D_DIM];
__device__ __nv_bfloat16 g_w2t_hi[(size_t)E_NUM * D_DIM * I_DIM];  // [E][D][I]
__device__ __nv_bfloat16 g_w2t_lo[(size_t)E_NUM * D_DIM * I_DIM];
__device__ __nv_bfloat16 g_mid_hi[(size_t)SLOTS * I_DIM];
__device__ __nv_bfloat16 g_mid_lo[(size_t)SLOTS * I_DIM];
__device__ float g_eout[(size_t)SLOTS * D_DIM];
__device__ int   g_sel[T_TOK * 2];
__device__ float g_wgt[T_TOK * 2];
__device__ int   g_slot[T_TOK * 2];
__device__ int   g_tok_of_slot[SLOTS];
__device__ int   g_counts[E_NUM];
__device__ int   g_cursor[E_NUM];
__device__ int   g_offsets[E_NUM];

// ---------------- PTX helpers ------------------------------------------------
__device__ __forceinline__ u32 smem_u32(const void* p) {
    u32 a;
    asm("{ .reg .u64 t; cvta.to.shared.u64 t, %1; cvt.u32.u64 %0, t; }"
        : "=r"(a) : "l"(p));
    return a;
}

#define CPA16(d, s) \
    asm volatile("cp.async.cg.shared.global [%0], [%1], 16;" \
                 :: "r"(d), "l"(s) : "memory")
#define CPA_COMMIT() asm volatile("cp.async.commit_group;" ::: "memory")
#define CPA_WAIT1()  asm volatile("cp.async.wait_group 1;" ::: "memory")
#define CPA_WAIT0()  asm volatile("cp.async.wait_group 0;" ::: "memory")

#define LDSM4(r0, r1, r2, r3, a) \
    asm volatile("ldmatrix.sync.aligned.m8n8.x4.shared.b16 {%0,%1,%2,%3}, [%4];" \
                 : "=r"(r0), "=r"(r1), "=r"(r2), "=r"(r3) : "r"(a))

#define MMA16816(c, a, b0, b1) \
    asm volatile("mma.sync.aligned.m16n8k16.row.col.f32.bf16.bf16.f32 " \
                 "{%0,%1,%2,%3}, {%4,%5,%6,%7}, {%8,%9}, {%0,%1,%2,%3};" \
                 : "+f"((c)[0]), "+f"((c)[1]), "+f"((c)[2]), "+f"((c)[3]) \
                 : "r"((a)[0]), "r"((a)[1]), "r"((a)[2]), "r"((a)[3]), \
                   "r"(b0), "r"(b1))

__device__ __forceinline__ float gelu_exact(float x) {
    return 0.5f * x * (1.0f + erff(x * 0.70710678118654752f));
}

__device__ __forceinline__ void split2(float x, float y, u32& hi, u32& lo) {
    __nv_bfloat16 h0 = __float2bfloat16(x), h1 = __float2bfloat16(y);
    __nv_bfloat16 l0 = __float2bfloat16(x - __bfloat162float(h0));
    __nv_bfloat16 l1 = __float2bfloat16(y - __bfloat162float(h1));
    hi = (u32)__bfloat16_as_ushort(h0) | ((u32)__bfloat16_as_ushort(h1) << 16);
    lo = (u32)__bfloat16_as_ushort(l0) | ((u32)__bfloat16_as_ushort(l1) << 16);
}

// ---------------- 0: init ---------------------------------------------------
__global__ void init_kernel() {
    int i = threadIdx.x;
    if (i < E_NUM) { g_counts[i] = 0; g_cursor[i] = 0; }
}

// ---------------- 1: gating + h split (fused) --------------------------------
__global__ void gate_kernel(const float* __restrict__ h,
                            const float* __restrict__ gw) {
    const int t = blockIdx.x;
    const int tid = threadIdx.x;
    const int warp = tid >> 5, lane = tid & 31;
    __shared__ float row[D_DIM];
    __shared__ float lg[E_NUM];

    // load row (coalesced), split to bf16 hi/lo, cache in smem
    float4 v = ((const float4*)(h + (size_t)t * D_DIM))[tid];
    u32 hi0, lo0, hi1, lo1;
    split2(v.x, v.y, hi0, lo0);
    split2(v.z, v.w, hi1, lo1);
    ((uint2*)g_h_hi)[(size_t)t * (D_DIM / 4) + tid] = make_uint2(hi0, hi1);
    ((uint2*)g_h_lo)[(size_t)t * (D_DIM / 4) + tid] = make_uint2(lo0, lo1);
    ((float4*)row)[tid] = v;
    __syncthreads();

    const float* gr = gw + (size_t)warp * D_DIM;
    float s = 0.f;
    for (int j = lane; j < D_DIM; j += 32) s += row[j] * gr[j];
    #pragma unroll
    for (int o = 16; o; o >>= 1) s += __shfl_xor_sync(0xffffffffu, s, o);
    if (lane == 0) lg[warp] = s;
    __syncthreads();
    if (tid == 0) {
        float m = lg[0];
        #pragma unroll
        for (int e = 1; e < E_NUM; e++) m = fmaxf(m, lg[e]);
        float p[E_NUM], den = 0.f;
        #pragma unroll
        for (int e = 0; e < E_NUM; e++) { p[e] = expf(lg[e] - m); den += p[e]; }
        float inv_den = 1.0f / den;
        #pragma unroll
        for (int e = 0; e < E_NUM; e++) p[e] *= inv_den;
        int i0 = 0;
        #pragma unroll
        for (int e = 1; e < E_NUM; e++) if (p[e] > p[i0]) i0 = e;
        int i1 = (i0 == 0) ? 1 : 0;
        #pragma unroll
        for (int e = 0; e < E_NUM; e++)
            if (e != i0 && e != i1 && p[e] > p[i1]) i1 = e;
        float w0 = p[i0], w1 = p[i1];
        float inv = 1.0f / (w0 + w1);
        g_sel[2 * t + 0] = i0; g_sel[2 * t + 1] = i1;
        g_wgt[2 * t + 0] = w0 * inv; g_wgt[2 * t + 1] = w1 * inv;
        atomicAdd(&g_counts[i0], 1);
        atomicAdd(&g_counts[i1], 1);
    }
}

// ---------------- 2: prefix sum + aux loss ----------------------------------
__global__ void prefix_kernel(float* aux_out) {
    if (threadIdx.x == 0) {
        int acc = 0; float aux = 0.f;
        #pragma unroll
        for (int e = 0; e < E_NUM; e++) {
            g_offsets[e] = acc; acc += g_counts[e];
            float u = (float)g_counts[e] / (float)T_TOK - 1.0f / (float)E_NUM;
            aux += u * u;
        }
        if (aux_out) *aux_out = aux / (float)E_NUM;
    }
}

// ---------------- 3: scatter ------------------------------------------------
__global__ void scatter_kernel() {
    int t = blockIdx.x * blockDim.x + threadIdx.x;
    if (t >= T_TOK) return;
    #pragma unroll
    for (int k = 0; k < 2; k++) {
        int e = g_sel[2 * t + k];
        int pos = atomicAdd(&g_cursor[e], 1);
        int s = g_offsets[e] + pos;
        g_tok_of_slot[s] = t;
        g_slot[2 * t + k] = s;
    }
}

// ---------------- 4: transpose + split weights -------------------------------
// W [E][KDIM][NDIM] fp32 -> [E][NDIM][KDIM] bf16 hi/lo, vectorized u32 stores.
template <bool W1>
__global__ void tsplit_kernel(const float* __restrict__ W) {
    const int KDIM = W1 ? D_DIM : I_DIM;
    const int NDIM = W1 ? I_DIM : D_DIM;
    __shared__ float t[64][33];
    const int e = blockIdx.z;
    const int n0 = blockIdx.x * 32, k0 = blockIdx.y * 64;
    const int tx = threadIdx.x, ty = threadIdx.y;   // (32, 8)
    const float* Wp = W + (size_t)e * KDIM * NDIM + n0 + tx;
    #pragma unroll
    for (int j = 0; j < 8; j++)
        t[ty + 8 * j][tx] = Wp[(size_t)(k0 + ty + 8 * j) * NDIM];
    __syncthreads();
    u32* oh = (u32*)(W1 ? g_w1t_hi : g_w2t_hi);
    u32* ol = (u32*)(W1 ? g_w1t_lo : g_w2t_lo);
    #pragma unroll
    for (int j = 0; j < 4; j++) {
        const int n = ty + 8 * j;
        float x0 = t[2 * tx][n], x1 = t[2 * tx + 1][n];
        u32 hi, lo;
        split2(x0, x1, hi, lo);
        size_t o = ((size_t)e * NDIM * KDIM + (size_t)(n0 + n) * KDIM + k0) / 2 + tx;
        oh[o] = hi; ol[o] = lo;
    }
}

// ---------------- 5/6: expert GEMMs via mma.sync (HMMA bf16, 3-pass) ---------
// Block tile 128x128x32, 256 thr, 8 warps (2m x 4n), warp tile 64x32.
// 2 stages x 4 matrices x 128 rows x 80B; 2 CTAs/SM target.
#define ROWB   80
#define MATB   (128 * ROWB)       // 10240
#define STAGEB (4 * MATB)         // 40960
#define GSMEM_BYTES (2 * STAGEB)  // 81920

template <int KD, int ND, bool FIRST>
__global__ void __launch_bounds__(256, 2)
mma_gemm_kernel(const float* __restrict__ bias) {
    const int e = blockIdx.z;
    const int cnt = g_counts[e];
    const int m0 = blockIdx.x * 128;
    if (m0 >= cnt) return;
    const int base = g_offsets[e];
    const int n0 = blockIdx.y * 128;

    extern __shared__ char smem[];
    const u32 sb = smem_u32(smem);

    const int tid  = threadIdx.x;
    const int lane = tid & 31, wid = tid >> 5;

    // ---- loader mapping: thread -> (row 0..127, k-half 0/1) ----
    const int lrow = tid >> 1;
    const int lkh  = (tid & 1) * 16;
    int am = m0 + lrow; if (am >= cnt) am = cnt - 1;
    const __nv_bfloat16 *pa_hi, *pa_lo;
    if (FIRST) {
        int tok = g_tok_of_slot[base + am];
        pa_hi = g_h_hi + (size_t)tok * KD;
        pa_lo = g_h_lo + (size_t)tok * KD;
    } else {
        pa_hi = g_mid_hi + (size_t)(base + am) * KD;
        pa_lo = g_mid_lo + (size_t)(base + am) * KD;
    }
    const __nv_bfloat16* pb_hi =
        (FIRST ? g_w1t_hi : g_w2t_hi) + ((size_t)e * ND + n0 + lrow) * KD;
    const __nv_bfloat16* pb_lo =
        (FIRST ? g_w1t_lo : g_w2t_lo) + ((size_t)e * ND + n0 + lrow) * KD;
    const u32 doff = (u32)(lrow * ROWB + (tid & 1) * 32);

    float c[4][4][4];
    #pragma unroll
    for (int i = 0; i < 4; i++)
        #pragma unroll
        for (int f = 0; f < 4; f++)
            #pragma unroll
            for (int q = 0; q < 4; q++) c[i][f][q] = 0.f;

    const int wm = (wid & 1) * 64;
    const int wn = (wid >> 1) * 32;
    const int l15 = lane & 15;
    const int lk16 = (lane >> 4) * 16;

    const int NK = KD / 32;

    // prologue: stage 0
    {
        const __nv_bfloat16* s0 = pa_hi + lkh;
        const __nv_bfloat16* s1 = pa_lo + lkh;
        const __nv_bfloat16* s2 = pb_hi + lkh;
        const __nv_bfloat16* s3 = pb_lo + lkh;
        u32 d = sb + doff;
        CPA16(d + 0 * MATB,      s0); CPA16(d + 0 * MATB + 16, s0 + 8);
        CPA16(d + 1 * MATB,      s1); CPA16(d + 1 * MATB + 16, s1 + 8);
        CPA16(d + 2 * MATB,      s2); CPA16(d + 2 * MATB + 16, s2 + 8);
        CPA16(d + 3 * MATB,      s3); CPA16(d + 3 * MATB + 16, s3 + 8);
    }
    CPA_COMMIT();

    #pragma unroll 1
    for (int kc = 0; kc < NK; kc++) {
        if (kc + 1 < NK) {
            const int kt = (kc + 1) * 32;
            const __nv_bfloat16* s0 = pa_hi + kt + lkh;
            const __nv_bfloat16* s1 = pa_lo + kt + lkh;
            const __nv_bfloat16* s2 = pb_hi + kt + lkh;
            const __nv_bfloat16* s3 = pb_lo + kt + lkh;
            u32 d = sb + ((kc + 1) & 1) * STAGEB + doff;
            CPA16(d + 0 * MATB,      s0); CPA16(d + 0 * MATB + 16, s0 + 8);
            CPA16(d + 1 * MATB,      s1); CPA16(d + 1 * MATB + 16, s1 + 8);
            CPA16(d + 2 * MATB,      s2); CPA16(d + 2 * MATB + 16, s2 + 8);
            CPA16(d + 3 * MATB,      s3); CPA16(d + 3 * MATB + 16, s3 + 8);
            CPA_COMMIT();
            CPA_WAIT1();
        } else {
            CPA_COMMIT();
            CPA_WAIT0();
        }
        __syncthreads();

        const u32 stb = sb + (kc & 1) * STAGEB;
        const u32 Ah = stb, Al = stb + MATB, Bh = stb + 2 * MATB, Bl = stb + 3 * MATB;

        #pragma unroll
        for (int s = 0; s < 2; s++) {
            const u32 koff = (u32)(s * 32 + lk16);

            // B hi + A hi, pass 1
            u32 bh[8];
            #pragma unroll
            for (int j = 0; j < 2; j++) {
                u32 rb = (u32)((wn + j * 16 + l15) * ROWB) + koff;
                LDSM4(bh[j*4+0], bh[j*4+1], bh[j*4+2], bh[j*4+3], Bh + rb);
            }
            u32 ah[4][4];
            #pragma unroll
            for (int i = 0; i < 4; i++) {
                u32 ra = (u32)((wm + i * 16 + l15) * ROWB) + koff;
                LDSM4(ah[i][0], ah[i][1], ah[i][2], ah[i][3], Ah + ra);
            }
            #pragma unroll
            for (int i = 0; i < 4; i++)
                #pragma unroll
                for (int f = 0; f < 4; f++) {
                    int j = f >> 1, r = f & 1;
                    MMA16816(c[i][f], ah[i], bh[j*4 + r], bh[j*4 + r + 2]);
                }

            // B lo, pass 2 (a_hi * b_lo)
            {
                u32 bl[8];
                #pragma unroll
                for (int j = 0; j < 2; j++) {
                    u32 rb = (u32)((wn + j * 16 + l15) * ROWB) + koff;
                    LDSM4(bl[j*4+0], bl[j*4+1], bl[j*4+2], bl[j*4+3], Bl + rb);
                }
                #pragma unroll
                for (int i = 0; i < 4; i++)
                    #pragma unroll
                    for (int f = 0; f < 4; f++) {
                        int j = f >> 1, r = f & 1;
                        MMA16816(c[i][f], ah[i], bl[j*4 + r], bl[j*4 + r + 2]);
                    }
            }

            // A lo, pass 3 (a_lo * b_hi)
            {
                u32 al[4][4];
                #pragma unroll
                for (int i = 0; i < 4; i++) {
                    u32 ra = (u32)((wm + i * 16 + l15) * ROWB) + koff;
                    LDSM4(al[i][0], al[i][1], al[i][2], al[i][3], Al + ra);
                }
                #pragma unroll
                for (int i = 0; i < 4; i++)
                    #pragma unroll
                    for (int f = 0; f < 4; f++) {
                        int j = f >> 1, r = f & 1;
                        MMA16816(c[i][f], al[i], bh[j*4 + r], bh[j*4 + r + 2]);
                    }
            }
        }
        __syncthreads();
    }

    // ---- epilogue ----
    #pragma unroll
    for (int f = 0; f < 4; f++) {
        const int ncol = n0 + wn + f * 8 + (lane & 3) * 2;
        const float bz0 = bias[(size_t)e * ND + ncol];
        const float bz1 = bias[(size_t)e * ND + ncol + 1];
        #pragma unroll
        for (int i = 0; i < 4; i++) {
            const int mr0 = m0 + wm + i * 16 + (lane >> 2);
            #pragma unroll
            for (int half = 0; half < 2; half++) {
                const int m = mr0 + half * 8;
                if (m >= cnt) continue;
                float v0 = c[i][f][half * 2 + 0] + bz0;
                float v1 = c[i][f][half * 2 + 1] + bz1;
                const size_t off = (size_t)(base + m) * ND + ncol;
                if (FIRST) {
                    float y0 = gelu_exact(v0), y1 = gelu_exact(v1);
                    u32 hi, lo;
                    split2(y0, y1, hi, lo);
                    *(u32*)(g_mid_hi + off) = hi;
                    *(u32*)(g_mid_lo + off) = lo;
                } else {
                    *(float2*)(g_eout + off) = make_float2(v0, v1);
                }
            }
        }
    }
}

// ---------------- 7: combine + residual + LayerNorm -------------------------
__device__ __forceinline__ float blockReduceSum256(float v) {
    __shared__ float sm[8];
    #pragma unroll
    for (int o = 16; o; o >>= 1) v += __shfl_xor_sync(0xffffffffu, v, o);
    if ((threadIdx.x & 31) == 0) sm[threadIdx.x >> 5] = v;
    __syncthreads();
    float r = sm[threadIdx.x & 7];
    #pragma unroll
    for (int o = 4; o; o >>= 1) r += __shfl_xor_sync(0xffffffffu, r, o);
    __syncthreads();
    return r;
}

__global__ void combine_ln_kernel(const float* __restrict__ h,
                                  const float* __restrict__ mask,
                                  const float* __restrict__ gamma,
                                  const float* __restrict__ beta,
                                  float* __restrict__ out) {
    const int t = blockIdx.x;
    const float mk = mask[t];
    const int s0 = g_slot[2 * t + 0], s1 = g_slot[2 * t + 1];
    const float w0 = g_wgt[2 * t + 0], w1 = g_wgt[2 * t + 1];
    const float* e0 = g_eout + (size_t)s0 * D_DIM;
    const float* e1 = g_eout + (size_t)s1 * D_DIM;
    const float* hr = h + (size_t)t * D_DIM;

    float y[4];
    float s = 0.f;
    #pragma unroll
    for (int j = 0; j < 4; j++) {
        int d = threadIdx.x + j * 256;
        y[j] = hr[d] + mk * (w0 * e0[d] + w1 * e1[d]);
        s += y[j];
    }
    float mean = blockReduceSum256(s) * (1.0f / D_DIM);
    float vs = 0.f;
    #pragma unroll
    for (int j = 0; j < 4; j++) { float cdev = y[j] - mean; vs += cdev * cdev; }
    float var = blockReduceSum256(vs) * (1.0f / D_DIM);
    float rs = rsqrtf(var + 1e-5f);
    #pragma unroll
    for (int j = 0; j < 4; j++) {
        int d = threadIdx.x + j * 256;
        out[(size_t)t * D_DIM + d] = (y[j] - mean) * rs * gamma[d] + beta[d];
    }
}

// ---------------- launch -----------------------------------------------------
extern "C" void kernel_launch(void* const* d_in, const int* in_sizes, int n_in,
                              void* d_out, int out_size) {
    const float* h     = (const float*)d_in[0];
    const float* mask  = (const float*)d_in[1];
    const float* gw    = (const float*)d_in[2];
    const float* w1    = (const float*)d_in[3];
    const float* b1    = (const float*)d_in[4];
    const float* w2    = (const float*)d_in[5];
    const float* b2    = (const float*)d_in[6];
    const float* gamma = (const float*)d_in[7];
    const float* beta  = (const float*)d_in[8];
    float* out = (float*)d_out;

    float* aux_ptr = (out_size > T_TOK * D_DIM) ? (out + (size_t)T_TOK * D_DIM)
                                                : nullptr;

    cudaFuncSetAttribute(mma_gemm_kernel<D_DIM, I_DIM, true>,
                         cudaFuncAttributeMaxDynamicSharedMemorySize, GSMEM_BYTES);
    cudaFuncSetAttribute(mma_gemm_kernel<I_DIM, D_DIM, false>,
                         cudaFuncAttributeMaxDynamicSharedMemorySize, GSMEM_BYTES);

    init_kernel<<<1, 32>>>();
    gate_kernel<<<T_TOK, 256>>>(h, gw);
    prefix_kernel<<<1, 1>>>(aux_ptr);
    scatter_kernel<<<(T_TOK + 255) / 256, 256>>>();

    { dim3 g(I_DIM / 32, D_DIM / 64, E_NUM); tsplit_kernel<true><<<g, dim3(32, 8)>>>(w1); }
    { dim3 g(D_DIM / 32, I_DIM / 64, E_NUM); tsplit_kernel<false><<<g, dim3(32, 8)>>>(w2); }

    // GEMM1: x = m-tiles, y = n-tiles
    { dim3 g(T_TOK / 128, I_DIM / 128, E_NUM);
      mma_gemm_kernel<D_DIM, I_DIM, true><<<g, 256, GSMEM_BYTES>>>(b1); }
    // GEMM2
    { dim3 g(T_TOK / 128, D_DIM / 128, E_NUM);
      mma_gemm_kernel<I_DIM, D_DIM, false><<<g, 256, GSMEM_BYTES>>>(b2); }

    combine_ln_kernel<<<T_TOK, 256>>>(h, mask, gamma, beta, out);
}

// round 6
// speedup vs baseline: 3.1843x; 1.4351x over previous
#include <cuda_runtime.h>
#include <cuda_fp16.h>
#include <math.h>

typedef unsigned int       u32;
typedef unsigned long long u64;

#define T_TOK 4096
#define D_DIM 1024
#define I_DIM 4096
#define E_NUM 8
#define SLOTS (2 * T_TOK)

// ---------------- scratch (device globals; no runtime allocation) ----------
__device__ __half g_h[(size_t)T_TOK * D_DIM];                      // A for GEMM1
__device__ __half g_w1t_hi[(size_t)E_NUM * I_DIM * D_DIM];         // [E][I][D]
__device__ __half g_w1t_lo[(size_t)E_NUM * I_DIM * D_DIM];
__device__ __half g_w2t_hi[(size_t)E_NUM * D_DIM * I_DIM];         // [E][D][I]
__device__ __half g_w2t_lo[(size_t)E_NUM * D_DIM * I_DIM];
__device__ __half g_mid[(size_t)SLOTS * I_DIM];                    // A for GEMM2
__device__ float g_eout[(size_t)SLOTS * D_DIM];
__device__ int   g_sel[T_TOK * 2];
__device__ float g_wgt[T_TOK * 2];
__device__ int   g_slot[T_TOK * 2];
__device__ int   g_tok_of_slot[SLOTS];
__device__ int   g_counts[E_NUM];
__device__ int   g_cursor[E_NUM];
__device__ int   g_offsets[E_NUM];

// ---------------- PTX helpers ------------------------------------------------
__device__ __forceinline__ u32 smem_u32(const void* p) {
    u32 a;
    asm("{ .reg .u64 t; cvta.to.shared.u64 t, %1; cvt.u32.u64 %0, t; }"
        : "=r"(a) : "l"(p));
    return a;
}

#define CPA16(d, s) \
    asm volatile("cp.async.cg.shared.global [%0], [%1], 16;" \
                 :: "r"(d), "l"(s) : "memory")
#define CPA_COMMIT() asm volatile("cp.async.commit_group;" ::: "memory")
#define CPA_WAIT1()  asm volatile("cp.async.wait_group 1;" ::: "memory")
#define CPA_WAIT0()  asm volatile("cp.async.wait_group 0;" ::: "memory")

#define LDSM4(r0, r1, r2, r3, a) \
    asm volatile("ldmatrix.sync.aligned.m8n8.x4.shared.b16 {%0,%1,%2,%3}, [%4];" \
                 : "=r"(r0), "=r"(r1), "=r"(r2), "=r"(r3) : "r"(a))

#define MMA16816(c, a, b0, b1) \
    asm volatile("mma.sync.aligned.m16n8k16.row.col.f32.f16.f16.f32 " \
                 "{%0,%1,%2,%3}, {%4,%5,%6,%7}, {%8,%9}, {%0,%1,%2,%3};" \
                 : "+f"((c)[0]), "+f"((c)[1]), "+f"((c)[2]), "+f"((c)[3]) \
                 : "r"((a)[0]), "r"((a)[1]), "r"((a)[2]), "r"((a)[3]), \
                   "r"(b0), "r"(b1))

__device__ __forceinline__ float gelu_exact(float x) {
    return 0.5f * x * (1.0f + erff(x * 0.70710678118654752f));
}

// pack two fp32 into fp16 pair (u32)
__device__ __forceinline__ u32 packh2(float x, float y) {
    __half2 p = __floats2half2_rn(x, y);
    return *(u32*)&p;
}
// two-term fp16 split (hi + lo) of pair
__device__ __forceinline__ void split2h(float x, float y, u32& hi, u32& lo) {
    __half h0 = __float2half_rn(x), h1 = __float2half_rn(y);
    __half l0 = __float2half_rn(x - __half2float(h0));
    __half l1 = __float2half_rn(y - __half2float(h1));
    hi = (u32)__half_as_ushort(h0) | ((u32)__half_as_ushort(h1) << 16);
    lo = (u32)__half_as_ushort(l0) | ((u32)__half_as_ushort(l1) << 16);
}

// ---------------- 0: init ---------------------------------------------------
__global__ void init_kernel() {
    int i = threadIdx.x;
    if (i < E_NUM) { g_counts[i] = 0; g_cursor[i] = 0; }
}

// ---------------- 1: gating + h->fp16 (fused) --------------------------------
__global__ void gate_kernel(const float* __restrict__ h,
                            const float* __restrict__ gw) {
    const int t = blockIdx.x;
    const int tid = threadIdx.x;
    const int warp = tid >> 5, lane = tid & 31;
    __shared__ float row[D_DIM];
    __shared__ float lg[E_NUM];

    float4 v = ((const float4*)(h + (size_t)t * D_DIM))[tid];
    u32 p0 = packh2(v.x, v.y);
    u32 p1 = packh2(v.z, v.w);
    ((uint2*)g_h)[(size_t)t * (D_DIM / 4) + tid] = make_uint2(p0, p1);
    ((float4*)row)[tid] = v;
    __syncthreads();

    const float* gr = gw + (size_t)warp * D_DIM;
    float s = 0.f;
    for (int j = lane; j < D_DIM; j += 32) s += row[j] * gr[j];
    #pragma unroll
    for (int o = 16; o; o >>= 1) s += __shfl_xor_sync(0xffffffffu, s, o);
    if (lane == 0) lg[warp] = s;
    __syncthreads();
    if (tid == 0) {
        float m = lg[0];
        #pragma unroll
        for (int e = 1; e < E_NUM; e++) m = fmaxf(m, lg[e]);
        float p[E_NUM], den = 0.f;
        #pragma unroll
        for (int e = 0; e < E_NUM; e++) { p[e] = expf(lg[e] - m); den += p[e]; }
        float inv_den = 1.0f / den;
        #pragma unroll
        for (int e = 0; e < E_NUM; e++) p[e] *= inv_den;
        int i0 = 0;
        #pragma unroll
        for (int e = 1; e < E_NUM; e++) if (p[e] > p[i0]) i0 = e;
        int i1 = (i0 == 0) ? 1 : 0;
        #pragma unroll
        for (int e = 0; e < E_NUM; e++)
            if (e != i0 && e != i1 && p[e] > p[i1]) i1 = e;
        float w0 = p[i0], w1 = p[i1];
        float inv = 1.0f / (w0 + w1);
        g_sel[2 * t + 0] = i0; g_sel[2 * t + 1] = i1;
        g_wgt[2 * t + 0] = w0 * inv; g_wgt[2 * t + 1] = w1 * inv;
        atomicAdd(&g_counts[i0], 1);
        atomicAdd(&g_counts[i1], 1);
    }
}

// ---------------- 2: prefix sum + aux loss ----------------------------------
__global__ void prefix_kernel(float* aux_out) {
    if (threadIdx.x == 0) {
        int acc = 0; float aux = 0.f;
        #pragma unroll
        for (int e = 0; e < E_NUM; e++) {
            g_offsets[e] = acc; acc += g_counts[e];
            float u = (float)g_counts[e] / (float)T_TOK - 1.0f / (float)E_NUM;
            aux += u * u;
        }
        if (aux_out) *aux_out = aux / (float)E_NUM;
    }
}

// ---------------- 3: scatter ------------------------------------------------
__global__ void scatter_kernel() {
    int t = blockIdx.x * blockDim.x + threadIdx.x;
    if (t >= T_TOK) return;
    #pragma unroll
    for (int k = 0; k < 2; k++) {
        int e = g_sel[2 * t + k];
        int pos = atomicAdd(&g_cursor[e], 1);
        int s = g_offsets[e] + pos;
        g_tok_of_slot[s] = t;
        g_slot[2 * t + k] = s;
    }
}

// ---------------- 4: transpose + split weights (fp16 hi/lo) ------------------
// W [E][KDIM][NDIM] fp32 -> [E][NDIM][KDIM] fp16 hi/lo
template <bool W1>
__global__ void tsplit_kernel(const float* __restrict__ W) {
    const int KDIM = W1 ? D_DIM : I_DIM;
    const int NDIM = W1 ? I_DIM : D_DIM;
    __shared__ float t[64][33];
    const int e = blockIdx.z;
    const int n0 = blockIdx.x * 32, k0 = blockIdx.y * 64;
    const int tx = threadIdx.x, ty = threadIdx.y;   // (32, 8)
    const float* Wp = W + (size_t)e * KDIM * NDIM + n0 + tx;
    #pragma unroll
    for (int j = 0; j < 8; j++)
        t[ty + 8 * j][tx] = Wp[(size_t)(k0 + ty + 8 * j) * NDIM];
    __syncthreads();
    u32* oh = (u32*)(W1 ? g_w1t_hi : g_w2t_hi);
    u32* ol = (u32*)(W1 ? g_w1t_lo : g_w2t_lo);
    #pragma unroll
    for (int j = 0; j < 4; j++) {
        const int n = ty + 8 * j;
        float x0 = t[2 * tx][n], x1 = t[2 * tx + 1][n];
        u32 hi, lo;
        split2h(x0, x1, hi, lo);
        size_t o = ((size_t)e * NDIM * KDIM + (size_t)(n0 + n) * KDIM + k0) / 2 + tx;
        oh[o] = hi; ol[o] = lo;
    }
}

// ---------------- 5/6: expert GEMMs via fp16 mma.sync (2-pass) ---------------
// C = A_f16 * (B_hi + B_lo). Block tile 128x128x32, 8 warps (2m x 4n).
// 2 stages x 3 matrices x 128 rows x 80B.
#define ROWB   80
#define MATB   (128 * ROWB)       // 10240
#define STAGEB (3 * MATB)         // 30720
#define GSMEM_BYTES (2 * STAGEB)  // 61440

template <int KD, int ND, bool FIRST>
__global__ void __launch_bounds__(256, 2)
mma_gemm_kernel(const float* __restrict__ bias) {
    const int e = blockIdx.z;
    const int cnt = g_counts[e];
    const int m0 = blockIdx.x * 128;
    if (m0 >= cnt) return;
    const int base = g_offsets[e];
    const int n0 = blockIdx.y * 128;

    extern __shared__ char smem[];
    const u32 sb = smem_u32(smem);

    const int tid  = threadIdx.x;
    const int lane = tid & 31, wid = tid >> 5;

    // ---- loader mapping: thread -> (row 0..127, k-half 0/1) ----
    const int lrow = tid >> 1;
    const int lkh  = (tid & 1) * 16;
    int am = m0 + lrow; if (am >= cnt) am = cnt - 1;
    const __half* pa;
    if (FIRST) {
        int tok = g_tok_of_slot[base + am];
        pa = g_h + (size_t)tok * KD;
    } else {
        pa = g_mid + (size_t)(base + am) * KD;
    }
    const __half* pb_hi =
        (FIRST ? g_w1t_hi : g_w2t_hi) + ((size_t)e * ND + n0 + lrow) * KD;
    const __half* pb_lo =
        (FIRST ? g_w1t_lo : g_w2t_lo) + ((size_t)e * ND + n0 + lrow) * KD;
    const u32 doff = (u32)(lrow * ROWB + (tid & 1) * 32);

    float c[4][4][4];
    #pragma unroll
    for (int i = 0; i < 4; i++)
        #pragma unroll
        for (int f = 0; f < 4; f++)
            #pragma unroll
            for (int q = 0; q < 4; q++) c[i][f][q] = 0.f;

    const int wm = (wid & 1) * 64;
    const int wn = (wid >> 1) * 32;
    const int l15 = lane & 15;
    const int lk16 = (lane >> 4) * 16;

    const int NK = KD / 32;

    // prologue: stage 0
    {
        const __half* s0 = pa + lkh;
        const __half* s1 = pb_hi + lkh;
        const __half* s2 = pb_lo + lkh;
        u32 d = sb + doff;
        CPA16(d + 0 * MATB, s0); CPA16(d + 0 * MATB + 16, s0 + 8);
        CPA16(d + 1 * MATB, s1); CPA16(d + 1 * MATB + 16, s1 + 8);
        CPA16(d + 2 * MATB, s2); CPA16(d + 2 * MATB + 16, s2 + 8);
    }
    CPA_COMMIT();

    #pragma unroll 1
    for (int kc = 0; kc < NK; kc++) {
        if (kc + 1 < NK) {
            const int kt = (kc + 1) * 32;
            const __half* s0 = pa + kt + lkh;
            const __half* s1 = pb_hi + kt + lkh;
            const __half* s2 = pb_lo + kt + lkh;
            u32 d = sb + ((kc + 1) & 1) * STAGEB + doff;
            CPA16(d + 0 * MATB, s0); CPA16(d + 0 * MATB + 16, s0 + 8);
            CPA16(d + 1 * MATB, s1); CPA16(d + 1 * MATB + 16, s1 + 8);
            CPA16(d + 2 * MATB, s2); CPA16(d + 2 * MATB + 16, s2 + 8);
            CPA_COMMIT();
            CPA_WAIT1();
        } else {
            CPA_COMMIT();
            CPA_WAIT0();
        }
        __syncthreads();

        const u32 stb = sb + (kc & 1) * STAGEB;
        const u32 Am = stb, Bh = stb + MATB, Bl = stb + 2 * MATB;

        #pragma unroll
        for (int s = 0; s < 2; s++) {
            const u32 koff = (u32)(s * 32 + lk16);

            u32 bh[8];
            #pragma unroll
            for (int j = 0; j < 2; j++) {
                u32 rb = (u32)((wn + j * 16 + l15) * ROWB) + koff;
                LDSM4(bh[j*4+0], bh[j*4+1], bh[j*4+2], bh[j*4+3], Bh + rb);
            }
            u32 ah[4][4];
            #pragma unroll
            for (int i = 0; i < 4; i++) {
                u32 ra = (u32)((wm + i * 16 + l15) * ROWB) + koff;
                LDSM4(ah[i][0], ah[i][1], ah[i][2], ah[i][3], Am + ra);
            }
            // pass 1: a * b_hi
            #pragma unroll
            for (int i = 0; i < 4; i++)
                #pragma unroll
                for (int f = 0; f < 4; f++) {
                    int j = f >> 1, r = f & 1;
                    MMA16816(c[i][f], ah[i], bh[j*4 + r], bh[j*4 + r + 2]);
                }
            // pass 2: a * b_lo
            {
                u32 bl[8];
                #pragma unroll
                for (int j = 0; j < 2; j++) {
                    u32 rb = (u32)((wn + j * 16 + l15) * ROWB) + koff;
                    LDSM4(bl[j*4+0], bl[j*4+1], bl[j*4+2], bl[j*4+3], Bl + rb);
                }
                #pragma unroll
                for (int i = 0; i < 4; i++)
                    #pragma unroll
                    for (int f = 0; f < 4; f++) {
                        int j = f >> 1, r = f & 1;
                        MMA16816(c[i][f], ah[i], bl[j*4 + r], bl[j*4 + r + 2]);
                    }
            }
        }
        __syncthreads();
    }

    // ---- epilogue ----
    #pragma unroll
    for (int f = 0; f < 4; f++) {
        const int ncol = n0 + wn + f * 8 + (lane & 3) * 2;
        const float bz0 = bias[(size_t)e * ND + ncol];
        const float bz1 = bias[(size_t)e * ND + ncol + 1];
        #pragma unroll
        for (int i = 0; i < 4; i++) {
            const int mr0 = m0 + wm + i * 16 + (lane >> 2);
            #pragma unroll
            for (int half = 0; half < 2; half++) {
                const int m = mr0 + half * 8;
                if (m >= cnt) continue;
                float v0 = c[i][f][half * 2 + 0] + bz0;
                float v1 = c[i][f][half * 2 + 1] + bz1;
                const size_t off = (size_t)(base + m) * ND + ncol;
                if (FIRST) {
                    float y0 = gelu_exact(v0), y1 = gelu_exact(v1);
                    *(u32*)(g_mid + off) = packh2(y0, y1);
                } else {
                    *(float2*)(g_eout + off) = make_float2(v0, v1);
                }
            }
        }
    }
}

// ---------------- 7: combine + residual + LayerNorm -------------------------
__device__ __forceinline__ float blockReduceSum256(float v) {
    __shared__ float sm[8];
    #pragma unroll
    for (int o = 16; o; o >>= 1) v += __shfl_xor_sync(0xffffffffu, v, o);
    if ((threadIdx.x & 31) == 0) sm[threadIdx.x >> 5] = v;
    __syncthreads();
    float r = sm[threadIdx.x & 7];
    #pragma unroll
    for (int o = 4; o; o >>= 1) r += __shfl_xor_sync(0xffffffffu, r, o);
    __syncthreads();
    return r;
}

__global__ void combine_ln_kernel(const float* __restrict__ h,
                                  const float* __restrict__ mask,
                                  const float* __restrict__ gamma,
                                  const float* __restrict__ beta,
                                  float* __restrict__ out) {
    const int t = blockIdx.x;
    const float mk = mask[t];
    const int s0 = g_slot[2 * t + 0], s1 = g_slot[2 * t + 1];
    const float w0 = g_wgt[2 * t + 0], w1 = g_wgt[2 * t + 1];
    const float* e0 = g_eout + (size_t)s0 * D_DIM;
    const float* e1 = g_eout + (size_t)s1 * D_DIM;
    const float* hr = h + (size_t)t * D_DIM;

    float y[4];
    float s = 0.f;
    #pragma unroll
    for (int j = 0; j < 4; j++) {
        int d = threadIdx.x + j * 256;
        y[j] = hr[d] + mk * (w0 * e0[d] + w1 * e1[d]);
        s += y[j];
    }
    float mean = blockReduceSum256(s) * (1.0f / D_DIM);
    float vs = 0.f;
    #pragma unroll
    for (int j = 0; j < 4; j++) { float cdev = y[j] - mean; vs += cdev * cdev; }
    float var = blockReduceSum256(vs) * (1.0f / D_DIM);
    float rs = rsqrtf(var + 1e-5f);
    #pragma unroll
    for (int j = 0; j < 4; j++) {
        int d = threadIdx.x + j * 256;
        out[(size_t)t * D_DIM + d] = (y[j] - mean) * rs * gamma[d] + beta[d];
    }
}

// ---------------- launch -----------------------------------------------------
extern "C" void kernel_launch(void* const* d_in, const int* in_sizes, int n_in,
                              void* d_out, int out_size) {
    const float* h     = (const float*)d_in[0];
    const float* mask  = (const float*)d_in[1];
    const float* gw    = (const float*)d_in[2];
    const float* w1    = (const float*)d_in[3];
    const float* b1    = (const float*)d_in[4];
    const float* w2    = (const float*)d_in[5];
    const float* b2    = (const float*)d_in[6];
    const float* gamma = (const float*)d_in[7];
    const float* beta  = (const float*)d_in[8];
    float* out = (float*)d_out;

    float* aux_ptr = (out_size > T_TOK * D_DIM) ? (out + (size_t)T_TOK * D_DIM)
                                                : nullptr;

    cudaFuncSetAttribute(mma_gemm_kernel<D_DIM, I_DIM, true>,
                         cudaFuncAttributeMaxDynamicSharedMemorySize, GSMEM_BYTES);
    cudaFuncSetAttribute(mma_gemm_kernel<I_DIM, D_DIM, false>,
                         cudaFuncAttributeMaxDynamicSharedMemorySize, GSMEM_BYTES);

    init_kernel<<<1, 32>>>();
    gate_kernel<<<T_TOK, 256>>>(h, gw);
    prefix_kernel<<<1, 1>>>(aux_ptr);
    scatter_kernel<<<(T_TOK + 255) / 256, 256>>>();

    { dim3 g(I_DIM / 32, D_DIM / 64, E_NUM); tsplit_kernel<true><<<g, dim3(32, 8)>>>(w1); }
    { dim3 g(D_DIM / 32, I_DIM / 64, E_NUM); tsplit_kernel<false><<<g, dim3(32, 8)>>>(w2); }

    // GEMM1: x = m-tiles, y = n-tiles
    { dim3 g(T_TOK / 128, I_DIM / 128, E_NUM);
      mma_gemm_kernel<D_DIM, I_DIM, true><<<g, 256, GSMEM_BYTES>>>(b1); }
    // GEMM2
    { dim3 g(T_TOK / 128, D_DIM / 128, E_NUM);
      mma_gemm_kernel<I_DIM, D_DIM, false><<<g, 256, GSMEM_BYTES>>>(b2); }

    combine_ln_kernel<<<T_TOK, 256>>>(h, mask, gamma, beta, out);
}

// round 7
// speedup vs baseline: 5.0497x; 1.5858x over previous
#include <cuda_runtime.h>
#include <cuda_fp16.h>
#include <math.h>

typedef unsigned int       u32;
typedef unsigned long long u64;

#define T_TOK 4096
#define D_DIM 1024
#define I_DIM 4096
#define E_NUM 8
#define SLOTS (2 * T_TOK)

// ---------------- scratch (device globals; no runtime allocation) ----------
__device__ __half g_h[(size_t)T_TOK * D_DIM];                      // A for GEMM1
__device__ __half g_w1t[(size_t)E_NUM * I_DIM * D_DIM];            // [E][I][D]
__device__ __half g_w2t[(size_t)E_NUM * D_DIM * I_DIM];            // [E][D][I]
__device__ __half g_mid[(size_t)SLOTS * I_DIM];                    // A for GEMM2
__device__ float g_eout[(size_t)SLOTS * D_DIM];
__device__ int   g_sel[T_TOK * 2];
__device__ float g_wgt[T_TOK * 2];
__device__ int   g_slot[T_TOK * 2];
__device__ int   g_tok_of_slot[SLOTS];
__device__ int   g_counts[E_NUM];
__device__ int   g_cursor[E_NUM];
__device__ int   g_offsets[E_NUM];

// ---------------- PTX helpers ------------------------------------------------
__device__ __forceinline__ u32 smem_u32(const void* p) {
    u32 a;
    asm("{ .reg .u64 t; cvta.to.shared.u64 t, %1; cvt.u32.u64 %0, t; }"
        : "=r"(a) : "l"(p));
    return a;
}

#define CPA16(d, s) \
    asm volatile("cp.async.cg.shared.global [%0], [%1], 16;" \
                 :: "r"(d), "l"(s) : "memory")
#define CPA_COMMIT() asm volatile("cp.async.commit_group;" ::: "memory")
#define CPA_WAIT1()  asm volatile("cp.async.wait_group 1;" ::: "memory")
#define CPA_WAIT0()  asm volatile("cp.async.wait_group 0;" ::: "memory")

#define LDSM4(r0, r1, r2, r3, a) \
    asm volatile("ldmatrix.sync.aligned.m8n8.x4.shared.b16 {%0,%1,%2,%3}, [%4];" \
                 : "=r"(r0), "=r"(r1), "=r"(r2), "=r"(r3) : "r"(a))

#define MMA16816(c, a, b0, b1) \
    asm volatile("mma.sync.aligned.m16n8k16.row.col.f32.f16.f16.f32 " \
                 "{%0,%1,%2,%3}, {%4,%5,%6,%7}, {%8,%9}, {%0,%1,%2,%3};" \
                 : "+f"((c)[0]), "+f"((c)[1]), "+f"((c)[2]), "+f"((c)[3]) \
                 : "r"((a)[0]), "r"((a)[1]), "r"((a)[2]), "r"((a)[3]), \
                   "r"(b0), "r"(b1))

__device__ __forceinline__ float gelu_exact(float x) {
    return 0.5f * x * (1.0f + erff(x * 0.70710678118654752f));
}

__device__ __forceinline__ u32 packh2(float x, float y) {
    __half2 p = __floats2half2_rn(x, y);
    return *(u32*)&p;
}

// ---------------- 0: init ---------------------------------------------------
__global__ void init_kernel() {
    int i = threadIdx.x;
    if (i < E_NUM) { g_counts[i] = 0; g_cursor[i] = 0; }
}

// ---------------- 1: gating + h->fp16 (fused) --------------------------------
__global__ void gate_kernel(const float* __restrict__ h,
                            const float* __restrict__ gw) {
    const int t = blockIdx.x;
    const int tid = threadIdx.x;
    const int warp = tid >> 5, lane = tid & 31;
    __shared__ float row[D_DIM];
    __shared__ float lg[E_NUM];

    float4 v = ((const float4*)(h + (size_t)t * D_DIM))[tid];
    u32 p0 = packh2(v.x, v.y);
    u32 p1 = packh2(v.z, v.w);
    ((uint2*)g_h)[(size_t)t * (D_DIM / 4) + tid] = make_uint2(p0, p1);
    ((float4*)row)[tid] = v;
    __syncthreads();

    const float* gr = gw + (size_t)warp * D_DIM;
    float s = 0.f;
    for (int j = lane; j < D_DIM; j += 32) s += row[j] * gr[j];
    #pragma unroll
    for (int o = 16; o; o >>= 1) s += __shfl_xor_sync(0xffffffffu, s, o);
    if (lane == 0) lg[warp] = s;
    __syncthreads();
    if (tid == 0) {
        float m = lg[0];
        #pragma unroll
        for (int e = 1; e < E_NUM; e++) m = fmaxf(m, lg[e]);
        float p[E_NUM], den = 0.f;
        #pragma unroll
        for (int e = 0; e < E_NUM; e++) { p[e] = expf(lg[e] - m); den += p[e]; }
        float inv_den = 1.0f / den;
        #pragma unroll
        for (int e = 0; e < E_NUM; e++) p[e] *= inv_den;
        int i0 = 0;
        #pragma unroll
        for (int e = 1; e < E_NUM; e++) if (p[e] > p[i0]) i0 = e;
        int i1 = (i0 == 0) ? 1 : 0;
        #pragma unroll
        for (int e = 0; e < E_NUM; e++)
            if (e != i0 && e != i1 && p[e] > p[i1]) i1 = e;
        float w0 = p[i0], w1 = p[i1];
        float inv = 1.0f / (w0 + w1);
        g_sel[2 * t + 0] = i0; g_sel[2 * t + 1] = i1;
        g_wgt[2 * t + 0] = w0 * inv; g_wgt[2 * t + 1] = w1 * inv;
        atomicAdd(&g_counts[i0], 1);
        atomicAdd(&g_counts[i1], 1);
    }
}

// ---------------- 2: prefix sum + aux loss ----------------------------------
__global__ void prefix_kernel(float* aux_out) {
    if (threadIdx.x == 0) {
        int acc = 0; float aux = 0.f;
        #pragma unroll
        for (int e = 0; e < E_NUM; e++) {
            g_offsets[e] = acc; acc += g_counts[e];
            float u = (float)g_counts[e] / (float)T_TOK - 1.0f / (float)E_NUM;
            aux += u * u;
        }
        if (aux_out) *aux_out = aux / (float)E_NUM;
    }
}

// ---------------- 3: scatter ------------------------------------------------
__global__ void scatter_kernel() {
    int t = blockIdx.x * blockDim.x + threadIdx.x;
    if (t >= T_TOK) return;
    #pragma unroll
    for (int k = 0; k < 2; k++) {
        int e = g_sel[2 * t + k];
        int pos = atomicAdd(&g_cursor[e], 1);
        int s = g_offsets[e] + pos;
        g_tok_of_slot[s] = t;
        g_slot[2 * t + k] = s;
    }
}

// ---------------- 4: transpose + convert weights to fp16 --------------------
// W [E][KDIM][NDIM] fp32 -> [E][NDIM][KDIM] fp16
template <bool W1>
__global__ void tsplit_kernel(const float* __restrict__ W) {
    const int KDIM = W1 ? D_DIM : I_DIM;
    const int NDIM = W1 ? I_DIM : D_DIM;
    __shared__ float t[64][33];
    const int e = blockIdx.z;
    const int n0 = blockIdx.x * 32, k0 = blockIdx.y * 64;
    const int tx = threadIdx.x, ty = threadIdx.y;   // (32, 8)
    const float* Wp = W + (size_t)e * KDIM * NDIM + n0 + tx;
    #pragma unroll
    for (int j = 0; j < 8; j++)
        t[ty + 8 * j][tx] = Wp[(size_t)(k0 + ty + 8 * j) * NDIM];
    __syncthreads();
    u32* oh = (u32*)(W1 ? g_w1t : g_w2t);
    #pragma unroll
    for (int j = 0; j < 4; j++) {
        const int n = ty + 8 * j;
        float x0 = t[2 * tx][n], x1 = t[2 * tx + 1][n];
        size_t o = ((size_t)e * NDIM * KDIM + (size_t)(n0 + n) * KDIM + k0) / 2 + tx;
        oh[o] = packh2(x0, x1);
    }
}

// ---------------- 5/6: expert GEMMs via fp16 mma.sync (1-pass) ---------------
// C = A_f16 * B_f16 (fp32 accum). Block tile 128x128x32, 8 warps (2m x 4n).
// 2 stages x 2 matrices x 128 rows x 80B.
#define ROWB   80
#define MATB   (128 * ROWB)       // 10240
#define STAGEB (2 * MATB)         // 20480
#define GSMEM_BYTES (2 * STAGEB)  // 40960

template <int KD, int ND, bool FIRST>
__global__ void __launch_bounds__(256, 2)
mma_gemm_kernel(const float* __restrict__ bias) {
    const int e = blockIdx.z;
    const int cnt = g_counts[e];
    const int m0 = blockIdx.x * 128;
    if (m0 >= cnt) return;
    const int base = g_offsets[e];
    const int n0 = blockIdx.y * 128;

    extern __shared__ char smem[];
    const u32 sb = smem_u32(smem);

    const int tid  = threadIdx.x;
    const int lane = tid & 31, wid = tid >> 5;

    // ---- loader mapping: thread -> (row 0..127, k-half 0/1) ----
    const int lrow = tid >> 1;
    const int lkh  = (tid & 1) * 16;
    int am = m0 + lrow; if (am >= cnt) am = cnt - 1;
    const __half* pa;
    if (FIRST) {
        int tok = g_tok_of_slot[base + am];
        pa = g_h + (size_t)tok * KD;
    } else {
        pa = g_mid + (size_t)(base + am) * KD;
    }
    const __half* pb =
        (FIRST ? g_w1t : g_w2t) + ((size_t)e * ND + n0 + lrow) * KD;
    const u32 doff = (u32)(lrow * ROWB + (tid & 1) * 32);

    float c[4][4][4];
    #pragma unroll
    for (int i = 0; i < 4; i++)
        #pragma unroll
        for (int f = 0; f < 4; f++)
            #pragma unroll
            for (int q = 0; q < 4; q++) c[i][f][q] = 0.f;

    const int wm = (wid & 1) * 64;
    const int wn = (wid >> 1) * 32;
    const int l15 = lane & 15;
    const int lk16 = (lane >> 4) * 16;

    const int NK = KD / 32;

    // prologue: stage 0
    {
        const __half* s0 = pa + lkh;
        const __half* s1 = pb + lkh;
        u32 d = sb + doff;
        CPA16(d,        s0); CPA16(d + 16,        s0 + 8);
        CPA16(d + MATB, s1); CPA16(d + MATB + 16, s1 + 8);
    }
    CPA_COMMIT();

    #pragma unroll 1
    for (int kc = 0; kc < NK; kc++) {
        if (kc + 1 < NK) {
            const int kt = (kc + 1) * 32;
            const __half* s0 = pa + kt + lkh;
            const __half* s1 = pb + kt + lkh;
            u32 d = sb + ((kc + 1) & 1) * STAGEB + doff;
            CPA16(d,        s0); CPA16(d + 16,        s0 + 8);
            CPA16(d + MATB, s1); CPA16(d + MATB + 16, s1 + 8);
            CPA_COMMIT();
            CPA_WAIT1();
        } else {
            CPA_COMMIT();
            CPA_WAIT0();
        }
        __syncthreads();

        const u32 stb = sb + (kc & 1) * STAGEB;
        const u32 Am = stb, Bm = stb + MATB;

        #pragma unroll
        for (int s = 0; s < 2; s++) {
            const u32 koff = (u32)(s * 32 + lk16);

            u32 bh[8];
            #pragma unroll
            for (int j = 0; j < 2; j++) {
                u32 rb = (u32)((wn + j * 16 + l15) * ROWB) + koff;
                LDSM4(bh[j*4+0], bh[j*4+1], bh[j*4+2], bh[j*4+3], Bm + rb);
            }
            u32 ah[4][4];
            #pragma unroll
            for (int i = 0; i < 4; i++) {
                u32 ra = (u32)((wm + i * 16 + l15) * ROWB) + koff;
                LDSM4(ah[i][0], ah[i][1], ah[i][2], ah[i][3], Am + ra);
            }
            #pragma unroll
            for (int i = 0; i < 4; i++)
                #pragma unroll
                for (int f = 0; f < 4; f++) {
                    int j = f >> 1, r = f & 1;
                    MMA16816(c[i][f], ah[i], bh[j*4 + r], bh[j*4 + r + 2]);
                }
        }
        __syncthreads();
    }

    // ---- epilogue ----
    #pragma unroll
    for (int f = 0; f < 4; f++) {
        const int ncol = n0 + wn + f * 8 + (lane & 3) * 2;
        const float bz0 = bias[(size_t)e * ND + ncol];
        const float bz1 = bias[(size_t)e * ND + ncol + 1];
        #pragma unroll
        for (int i = 0; i < 4; i++) {
            const int mr0 = m0 + wm + i * 16 + (lane >> 2);
            #pragma unroll
            for (int half = 0; half < 2; half++) {
                const int m = mr0 + half * 8;
                if (m >= cnt) continue;
                float v0 = c[i][f][half * 2 + 0] + bz0;
                float v1 = c[i][f][half * 2 + 1] + bz1;
                const size_t off = (size_t)(base + m) * ND + ncol;
                if (FIRST) {
                    float y0 = gelu_exact(v0), y1 = gelu_exact(v1);
                    *(u32*)(g_mid + off) = packh2(y0, y1);
                } else {
                    *(float2*)(g_eout + off) = make_float2(v0, v1);
                }
            }
        }
    }
}

// ---------------- 7: combine + residual + LayerNorm -------------------------
__device__ __forceinline__ float blockReduceSum256(float v) {
    __shared__ float sm[8];
    #pragma unroll
    for (int o = 16; o; o >>= 1) v += __shfl_xor_sync(0xffffffffu, v, o);
    if ((threadIdx.x & 31) == 0) sm[threadIdx.x >> 5] = v;
    __syncthreads();
    float r = sm[threadIdx.x & 7];
    #pragma unroll
    for (int o = 4; o; o >>= 1) r += __shfl_xor_sync(0xffffffffu, r, o);
    __syncthreads();
    return r;
}

__global__ void combine_ln_kernel(const float* __restrict__ h,
                                  const float* __restrict__ mask,
                                  const float* __restrict__ gamma,
                                  const float* __restrict__ beta,
                                  float* __restrict__ out) {
    const int t = blockIdx.x;
    const float mk = mask[t];
    const int s0 = g_slot[2 * t + 0], s1 = g_slot[2 * t + 1];
    const float w0 = g_wgt[2 * t + 0], w1 = g_wgt[2 * t + 1];
    const float* e0 = g_eout + (size_t)s0 * D_DIM;
    const float* e1 = g_eout + (size_t)s1 * D_DIM;
    const float* hr = h + (size_t)t * D_DIM;

    float y[4];
    float s = 0.f;
    #pragma unroll
    for (int j = 0; j < 4; j++) {
        int d = threadIdx.x + j * 256;
        y[j] = hr[d] + mk * (w0 * e0[d] + w1 * e1[d]);
        s += y[j];
    }
    float mean = blockReduceSum256(s) * (1.0f / D_DIM);
    float vs = 0.f;
    #pragma unroll
    for (int j = 0; j < 4; j++) { float cdev = y[j] - mean; vs += cdev * cdev; }
    float var = blockReduceSum256(vs) * (1.0f / D_DIM);
    float rs = rsqrtf(var + 1e-5f);
    #pragma unroll
    for (int j = 0; j < 4; j++) {
        int d = threadIdx.x + j * 256;
        out[(size_t)t * D_DIM + d] = (y[j] - mean) * rs * gamma[d] + beta[d];
    }
}

// ---------------- launch -----------------------------------------------------
extern "C" void kernel_launch(void* const* d_in, const int* in_sizes, int n_in,
                              void* d_out, int out_size) {
    const float* h     = (const float*)d_in[0];
    const float* mask  = (const float*)d_in[1];
    const float* gw    = (const float*)d_in[2];
    const float* w1    = (const float*)d_in[3];
    const float* b1    = (const float*)d_in[4];
    const float* w2    = (const float*)d_in[5];
    const float* b2    = (const float*)d_in[6];
    const float* gamma = (const float*)d_in[7];
    const float* beta  = (const float*)d_in[8];
    float* out = (float*)d_out;

    float* aux_ptr = (out_size > T_TOK * D_DIM) ? (out + (size_t)T_TOK * D_DIM)
                                                : nullptr;

    cudaFuncSetAttribute(mma_gemm_kernel<D_DIM, I_DIM, true>,
                         cudaFuncAttributeMaxDynamicSharedMemorySize, GSMEM_BYTES);
    cudaFuncSetAttribute(mma_gemm_kernel<I_DIM, D_DIM, false>,
                         cudaFuncAttributeMaxDynamicSharedMemorySize, GSMEM_BYTES);

    init_kernel<<<1, 32>>>();
    gate_kernel<<<T_TOK, 256>>>(h, gw);
    prefix_kernel<<<1, 1>>>(aux_ptr);
    scatter_kernel<<<(T_TOK + 255) / 256, 256>>>();

    { dim3 g(I_DIM / 32, D_DIM / 64, E_NUM); tsplit_kernel<true><<<g, dim3(32, 8)>>>(w1); }
    { dim3 g(D_DIM / 32, I_DIM / 64, E_NUM); tsplit_kernel<false><<<g, dim3(32, 8)>>>(w2); }

    // GEMM1: x = m-tiles, y = n-tiles
    { dim3 g(T_TOK / 128, I_DIM / 128, E_NUM);
      mma_gemm_kernel<D_DIM, I_DIM, true><<<g, 256, GSMEM_BYTES>>>(b1); }
    // GEMM2
    { dim3 g(T_TOK / 128, D_DIM / 128, E_NUM);
      mma_gemm_kernel<I_DIM, D_DIM, false><<<g, 256, GSMEM_BYTES>>>(b2); }

    combine_ln_kernel<<<T_TOK, 256>>>(h, mask, gamma, beta, out);
}